// round 1
// baseline (speedup 1.0000x reference)
#include <cuda_runtime.h>
#include <cuda_bf16.h>
#include <math.h>

// ---------------- problem constants ----------------
#define BB 4
#define TT 1024
#define EE 768
#define HH 8
#define HS 96
#define LL 8
#define VV 32000
#define FF 3072            // 4*E
#define MM (BB*TT)         // 4096 rows

// ---------------- scratch (device globals; no allocation allowed) ----------------
__device__ float g_x  [(size_t)MM*EE];
__device__ float g_xn [(size_t)MM*EE];
__device__ float g_q  [(size_t)MM*EE];
__device__ float g_k  [(size_t)MM*EE];
__device__ float g_v  [(size_t)MM*EE];
__device__ float g_att[(size_t)MM*EE];
__device__ float g_h4 [(size_t)MM*FF];
__device__ float g_logits_scratch[(size_t)MM*VV];   // used only if d_out can't hold logits

// ---------------- embedding ----------------
__global__ void embed_kernel(const int* __restrict__ idx,
                             const float* __restrict__ tok,
                             const float* __restrict__ pos,
                             float* __restrict__ x)
{
    size_t i = (size_t)blockIdx.x * blockDim.x + threadIdx.x;
    if (i >= (size_t)MM * EE) return;
    int e  = (int)(i % EE);
    int bt = (int)(i / EE);
    int t  = bt % TT;
    x[i] = tok[(size_t)idx[bt] * EE + e] + pos[(size_t)t * EE + e];
}

// ---------------- layernorm (one block per row) ----------------
__global__ void ln_kernel(const float* __restrict__ x,
                          const float* __restrict__ g,
                          const float* __restrict__ b,
                          float* __restrict__ out)
{
    int row = blockIdx.x;
    int tid = threadIdx.x;  // 256
    const float* xr = x + (size_t)row * EE;
    float s = 0.f, s2 = 0.f;
    for (int e = tid; e < EE; e += 256) { float v = xr[e]; s += v; s2 += v * v; }
    __shared__ float r1[256], r2[256];
    r1[tid] = s; r2[tid] = s2; __syncthreads();
    for (int o = 128; o > 0; o >>= 1) {
        if (tid < o) { r1[tid] += r1[tid + o]; r2[tid] += r2[tid + o]; }
        __syncthreads();
    }
    float mean = r1[0] * (1.f / EE);
    float var  = r2[0] * (1.f / EE) - mean * mean;
    float inv  = rsqrtf(var + 1e-5f);
    float* orow = out + (size_t)row * EE;
    for (int e = tid; e < EE; e += 256)
        orow[e] = (xr[e] - mean) * inv * g[e] + b[e];
}

// ---------------- GEMM: C[M,N] = A[M,K] @ op(B) (+bias)(+GELU)(+res) ----------------
// TRB=false: B is [K,N] row-major.  TRB=true: B is [N,K] row-major (C = A @ B^T).
// M,N multiples of 128; K multiple of 8 (true for all shapes here).
template<bool TRB, bool DOGELU>
__global__ void __launch_bounds__(256, 2)
gemm_kernel(const float* __restrict__ A, const float* __restrict__ B,
            const float* __restrict__ bias, const float* __restrict__ res,
            float* __restrict__ C, int M, int N, int K)
{
    __shared__ float As[8][128];
    __shared__ float Bs[8][128];

    const int t   = threadIdx.x;
    const int ty  = t >> 4;          // 0..15
    const int tx  = t & 15;          // 0..15
    const int row0 = blockIdx.y * 128;
    const int col0 = blockIdx.x * 128;

    float acc[8][8];
#pragma unroll
    for (int i = 0; i < 8; i++)
#pragma unroll
        for (int j = 0; j < 8; j++) acc[i][j] = 0.f;

    for (int k0 = 0; k0 < K; k0 += 8) {
        // load A tile 128x8 -> As[k][m]
        {
            int ar = t >> 1;
            int ac = (t & 1) * 4;
            float4 va = *(const float4*)&A[(size_t)(row0 + ar) * K + k0 + ac];
            As[ac + 0][ar] = va.x; As[ac + 1][ar] = va.y;
            As[ac + 2][ar] = va.z; As[ac + 3][ar] = va.w;
        }
        if (!TRB) {
            // B tile 8x128 -> Bs[k][n]
            int br = t >> 5;
            int bc = (t & 31) * 4;
            float4 vb = *(const float4*)&B[(size_t)(k0 + br) * N + col0 + bc];
            *(float4*)&Bs[br][bc] = vb;
        } else {
            // B is [N,K]: tile 128(n) x 8(k) -> Bs[k][n]
            int br = t >> 1;
            int bc = (t & 1) * 4;
            float4 vb = *(const float4*)&B[(size_t)(col0 + br) * K + k0 + bc];
            Bs[bc + 0][br] = vb.x; Bs[bc + 1][br] = vb.y;
            Bs[bc + 2][br] = vb.z; Bs[bc + 3][br] = vb.w;
        }
        __syncthreads();

#pragma unroll
        for (int kk = 0; kk < 8; kk++) {
            float a[8], b[8];
            *(float4*)(a)     = *(const float4*)&As[kk][ty * 8];
            *(float4*)(a + 4) = *(const float4*)&As[kk][ty * 8 + 4];
            *(float4*)(b)     = *(const float4*)&Bs[kk][tx * 8];
            *(float4*)(b + 4) = *(const float4*)&Bs[kk][tx * 8 + 4];
#pragma unroll
            for (int i = 0; i < 8; i++)
#pragma unroll
                for (int j = 0; j < 8; j++)
                    acc[i][j] = fmaf(a[i], b[j], acc[i][j]);
        }
        __syncthreads();
    }

#pragma unroll
    for (int i = 0; i < 8; i++) {
        int gr = row0 + ty * 8 + i;
#pragma unroll
        for (int j = 0; j < 8; j++) {
            int gc = col0 + tx * 8 + j;
            float c = acc[i][j];
            if (bias) c += bias[gc];
            if (DOGELU) c = 0.5f * c * (1.f + erff(c * 0.70710678118654752f));
            if (res)  c += res[(size_t)gr * N + gc];
            C[(size_t)gr * N + gc] = c;
        }
    }
}

// ---------------- attention: one block per (b,h,tq), 128 threads ----------------
__global__ void attn_kernel(const float* __restrict__ q,
                            const float* __restrict__ k,
                            const float* __restrict__ v,
                            float* __restrict__ out)
{
    const int tq  = blockIdx.x;
    const int h   = blockIdx.y;
    const int b   = blockIdx.z;
    const int tid = threadIdx.x;   // 128

    __shared__ float qs[HS];
    __shared__ float sc[TT];
    __shared__ float red[128];

    const size_t base = (size_t)b * TT * EE + (size_t)h * HS;

    if (tid < HS) qs[tid] = q[base + (size_t)tq * EE + tid];
    __syncthreads();

    const float scale = 0.102062072615966f;  // 96^-0.5
    float lmax = -1e30f;
    for (int s = tid; s <= tq; s += 128) {
        const float* kr = &k[base + (size_t)s * EE];
        float d = 0.f;
#pragma unroll
        for (int e = 0; e < HS; e++) d = fmaf(qs[e], kr[e], d);
        d *= scale;
        sc[s] = d;
        lmax = fmaxf(lmax, d);
    }
    red[tid] = lmax; __syncthreads();
    for (int o = 64; o > 0; o >>= 1) {
        if (tid < o) red[tid] = fmaxf(red[tid], red[tid + o]);
        __syncthreads();
    }
    const float m = red[0];
    __syncthreads();

    float lsum = 0.f;
    for (int s = tid; s <= tq; s += 128) {
        float p = expf(sc[s] - m);
        sc[s] = p;
        lsum += p;
    }
    red[tid] = lsum; __syncthreads();
    for (int o = 64; o > 0; o >>= 1) {
        if (tid < o) red[tid] += red[tid + o];
        __syncthreads();
    }
    const float inv = 1.f / red[0];

    for (int d0 = tid; d0 < HS; d0 += 128) {
        float acc = 0.f;
        for (int s = 0; s <= tq; s++)
            acc = fmaf(sc[s], v[base + (size_t)s * EE + d0], acc);
        out[base + (size_t)tq * EE + d0] = acc * inv;
    }
}

// ---------------- loss ----------------
__global__ void loss_zero_kernel(float* loss) { *loss = 0.f; }

__global__ void loss_kernel(const float* __restrict__ logits,
                            const int* __restrict__ targets,
                            float* __restrict__ loss)
{
    const int row = blockIdx.x;
    const int tid = threadIdx.x;   // 256
    const float* lr = logits + (size_t)row * VV;

    __shared__ float red[256];
    float lmax = -1e30f;
    for (int j = tid; j < VV; j += 256) lmax = fmaxf(lmax, lr[j]);
    red[tid] = lmax; __syncthreads();
    for (int o = 128; o > 0; o >>= 1) {
        if (tid < o) red[tid] = fmaxf(red[tid], red[tid + o]);
        __syncthreads();
    }
    const float m = red[0];
    __syncthreads();

    float lsum = 0.f;
    for (int j = tid; j < VV; j += 256) lsum += expf(lr[j] - m);
    red[tid] = lsum; __syncthreads();
    for (int o = 128; o > 0; o >>= 1) {
        if (tid < o) red[tid] += red[tid + o];
        __syncthreads();
    }
    if (tid == 0) {
        float lp = lr[targets[row]] - m - logf(red[0]);
        atomicAdd(loss, -lp * (1.f / (float)MM));
    }
}

// ---------------- launch ----------------
extern "C" void kernel_launch(void* const* d_in, const int* in_sizes, int n_in,
                              void* d_out, int out_size)
{
    const int*   idx     = (const int*)  d_in[0];
    const int*   targets = (const int*)  d_in[1];
    const float* tok     = (const float*)d_in[2];
    const float* pos     = (const float*)d_in[3];
    const float* Wq      = (const float*)d_in[4];
    const float* Wk      = (const float*)d_in[5];
    const float* Wv      = (const float*)d_in[6];
    const float* Wo      = (const float*)d_in[7];
    const float* bo      = (const float*)d_in[8];
    const float* ln1_g   = (const float*)d_in[9];
    const float* ln1_b   = (const float*)d_in[10];
    const float* ln2_g   = (const float*)d_in[11];
    const float* ln2_b   = (const float*)d_in[12];
    const float* W1      = (const float*)d_in[13];
    const float* b1      = (const float*)d_in[14];
    const float* W2      = (const float*)d_in[15];
    const float* b2      = (const float*)d_in[16];
    const float* lnf_g   = (const float*)d_in[17];
    const float* lnf_b   = (const float*)d_in[18];

    float *x, *xn, *q, *k, *v, *att, *h4, *lg_scratch;
    cudaGetSymbolAddress((void**)&x,   g_x);
    cudaGetSymbolAddress((void**)&xn,  g_xn);
    cudaGetSymbolAddress((void**)&q,   g_q);
    cudaGetSymbolAddress((void**)&k,   g_k);
    cudaGetSymbolAddress((void**)&v,   g_v);
    cudaGetSymbolAddress((void**)&att, g_att);
    cudaGetSymbolAddress((void**)&h4,  g_h4);
    cudaGetSymbolAddress((void**)&lg_scratch, g_logits_scratch);

    const bool out_holds_logits = ((long long)out_size >= (long long)MM * VV);
    float* logits = out_holds_logits ? (float*)d_out : lg_scratch;

    // embedding
    {
        size_t n = (size_t)MM * EE;
        embed_kernel<<<(unsigned)((n + 255) / 256), 256>>>(idx, tok, pos, x);
    }

    const dim3 gE(EE / 128, MM / 128);   // N=768
    const dim3 gF(FF / 128, MM / 128);   // N=3072
    const dim3 gV(VV / 128, MM / 128);   // N=32000

    for (int l = 0; l < LL; l++) {
        const size_t oEE = (size_t)l * EE * EE;
        ln_kernel<<<MM, 256>>>(x, ln1_g + (size_t)l * EE, ln1_b + (size_t)l * EE, xn);
        gemm_kernel<false, false><<<gE, 256>>>(xn, Wq + oEE, nullptr, nullptr, q, MM, EE, EE);
        gemm_kernel<false, false><<<gE, 256>>>(xn, Wk + oEE, nullptr, nullptr, k, MM, EE, EE);
        gemm_kernel<false, false><<<gE, 256>>>(xn, Wv + oEE, nullptr, nullptr, v, MM, EE, EE);
        attn_kernel<<<dim3(TT, HH, BB), 128>>>(q, k, v, att);
        // x = x + att @ Wo + bo   (residual fused, in-place safe: 1 writer per element)
        gemm_kernel<false, false><<<gE, 256>>>(att, Wo + oEE, bo + (size_t)l * EE, x, x, MM, EE, EE);

        ln_kernel<<<MM, 256>>>(x, ln2_g + (size_t)l * EE, ln2_b + (size_t)l * EE, xn);
        gemm_kernel<false, true ><<<gF, 256>>>(xn, W1 + (size_t)l * EE * FF,
                                               b1 + (size_t)l * FF, nullptr, h4, MM, FF, EE);
        gemm_kernel<false, false><<<gE, 256>>>(h4, W2 + (size_t)l * FF * EE,
                                               b2 + (size_t)l * EE, x, x, MM, EE, FF);
    }

    ln_kernel<<<MM, 256>>>(x, lnf_g, lnf_b, xn);
    // logits = xn @ tok^T  (tied head, NT)
    gemm_kernel<true, false><<<gV, 256>>>(xn, tok, nullptr, nullptr, logits, MM, VV, EE);

    // loss -> last element of d_out (after logits) or d_out[0] if out is just the loss
    float* loss_ptr = out_holds_logits ? ((float*)d_out + (size_t)MM * VV)
                                       : (float*)d_out;
    if (!out_holds_logits || (long long)out_size > (long long)MM * VV) {
        loss_zero_kernel<<<1, 1>>>(loss_ptr);
        loss_kernel<<<MM, 256>>>(logits, targets, loss_ptr);
    }
}

// round 2
// speedup vs baseline: 1.0001x; 1.0001x over previous
#include <cuda_runtime.h>
#include <cuda_bf16.h>
#include <math.h>

// ---------------- problem constants ----------------
#define BB 4
#define TT 1024
#define EE 768
#define HH 8
#define HS 96
#define LL 8
#define VV 32000
#define FF 3072            // 4*E
#define MM (BB*TT)         // 4096 rows

// ---------------- scratch (device globals; no allocation allowed) ----------------
__device__ float g_x  [(size_t)MM*EE];
__device__ float g_xn [(size_t)MM*EE];
__device__ float g_q  [(size_t)MM*EE];
__device__ float g_k  [(size_t)MM*EE];
__device__ float g_v  [(size_t)MM*EE];
__device__ float g_att[(size_t)MM*EE];
__device__ float g_h4 [(size_t)MM*FF];
__device__ float g_logits_scratch[(size_t)MM*VV];   // used only if d_out can't hold logits

// ---------------- embedding ----------------
__global__ void embed_kernel(const int* __restrict__ idx,
                             const float* __restrict__ tok,
                             const float* __restrict__ pos,
                             float* __restrict__ x)
{
    size_t i = (size_t)blockIdx.x * blockDim.x + threadIdx.x;
    if (i >= (size_t)MM * EE) return;
    int e  = (int)(i % EE);
    int bt = (int)(i / EE);
    int t  = bt % TT;
    x[i] = tok[(size_t)idx[bt] * EE + e] + pos[(size_t)t * EE + e];
}

// ---------------- layernorm (one block per row) ----------------
__global__ void ln_kernel(const float* __restrict__ x,
                          const float* __restrict__ g,
                          const float* __restrict__ b,
                          float* __restrict__ out)
{
    int row = blockIdx.x;
    int tid = threadIdx.x;  // 256
    const float* xr = x + (size_t)row * EE;
    float s = 0.f, s2 = 0.f;
    for (int e = tid; e < EE; e += 256) { float v = xr[e]; s += v; s2 += v * v; }
    __shared__ float r1[256], r2[256];
    r1[tid] = s; r2[tid] = s2; __syncthreads();
    for (int o = 128; o > 0; o >>= 1) {
        if (tid < o) { r1[tid] += r1[tid + o]; r2[tid] += r2[tid + o]; }
        __syncthreads();
    }
    float mean = r1[0] * (1.f / EE);
    float var  = r2[0] * (1.f / EE) - mean * mean;
    float inv  = rsqrtf(var + 1e-5f);
    float* orow = out + (size_t)row * EE;
    for (int e = tid; e < EE; e += 256)
        orow[e] = (xr[e] - mean) * inv * g[e] + b[e];
}

// ---------------- GEMM: C[M,N] = A[M,K] @ op(B) (+bias)(+GELU)(+res) ----------------
// TRB=false: B is [K,N] row-major.  TRB=true: B is [N,K] row-major (C = A @ B^T).
// M,N multiples of 128; K multiple of 8 (true for all shapes here).
template<bool TRB, bool DOGELU>
__global__ void __launch_bounds__(256, 2)
gemm_kernel(const float* __restrict__ A, const float* __restrict__ B,
            const float* __restrict__ bias, const float* __restrict__ res,
            float* __restrict__ C, int M, int N, int K)
{
    __shared__ float As[8][128];
    __shared__ float Bs[8][128];

    const int t   = threadIdx.x;
    const int ty  = t >> 4;          // 0..15
    const int tx  = t & 15;          // 0..15
    const int row0 = blockIdx.y * 128;
    const int col0 = blockIdx.x * 128;

    float acc[8][8];
#pragma unroll
    for (int i = 0; i < 8; i++)
#pragma unroll
        for (int j = 0; j < 8; j++) acc[i][j] = 0.f;

    for (int k0 = 0; k0 < K; k0 += 8) {
        // load A tile 128x8 -> As[k][m]
        {
            int ar = t >> 1;
            int ac = (t & 1) * 4;
            float4 va = *(const float4*)&A[(size_t)(row0 + ar) * K + k0 + ac];
            As[ac + 0][ar] = va.x; As[ac + 1][ar] = va.y;
            As[ac + 2][ar] = va.z; As[ac + 3][ar] = va.w;
        }
        if (!TRB) {
            // B tile 8x128 -> Bs[k][n]
            int br = t >> 5;
            int bc = (t & 31) * 4;
            float4 vb = *(const float4*)&B[(size_t)(k0 + br) * N + col0 + bc];
            *(float4*)&Bs[br][bc] = vb;
        } else {
            // B is [N,K]: tile 128(n) x 8(k) -> Bs[k][n]
            int br = t >> 1;
            int bc = (t & 1) * 4;
            float4 vb = *(const float4*)&B[(size_t)(col0 + br) * K + k0 + bc];
            Bs[bc + 0][br] = vb.x; Bs[bc + 1][br] = vb.y;
            Bs[bc + 2][br] = vb.z; Bs[bc + 3][br] = vb.w;
        }
        __syncthreads();

#pragma unroll
        for (int kk = 0; kk < 8; kk++) {
            float a[8], b[8];
            *(float4*)(a)     = *(const float4*)&As[kk][ty * 8];
            *(float4*)(a + 4) = *(const float4*)&As[kk][ty * 8 + 4];
            *(float4*)(b)     = *(const float4*)&Bs[kk][tx * 8];
            *(float4*)(b + 4) = *(const float4*)&Bs[kk][tx * 8 + 4];
#pragma unroll
            for (int i = 0; i < 8; i++)
#pragma unroll
                for (int j = 0; j < 8; j++)
                    acc[i][j] = fmaf(a[i], b[j], acc[i][j]);
        }
        __syncthreads();
    }

#pragma unroll
    for (int i = 0; i < 8; i++) {
        int gr = row0 + ty * 8 + i;
#pragma unroll
        for (int j = 0; j < 8; j++) {
            int gc = col0 + tx * 8 + j;
            float c = acc[i][j];
            if (bias) c += bias[gc];
            if (DOGELU) c = 0.5f * c * (1.f + erff(c * 0.70710678118654752f));
            if (res)  c += res[(size_t)gr * N + gc];
            C[(size_t)gr * N + gc] = c;
        }
    }
}

// ---------------- attention: one block per (b,h,tq), 128 threads ----------------
__global__ void attn_kernel(const float* __restrict__ q,
                            const float* __restrict__ k,
                            const float* __restrict__ v,
                            float* __restrict__ out)
{
    const int tq  = blockIdx.x;
    const int h   = blockIdx.y;
    const int b   = blockIdx.z;
    const int tid = threadIdx.x;   // 128

    __shared__ float qs[HS];
    __shared__ float sc[TT];
    __shared__ float red[128];

    const size_t base = (size_t)b * TT * EE + (size_t)h * HS;

    if (tid < HS) qs[tid] = q[base + (size_t)tq * EE + tid];
    __syncthreads();

    const float scale = 0.102062072615966f;  // 96^-0.5
    float lmax = -1e30f;
    for (int s = tid; s <= tq; s += 128) {
        const float* kr = &k[base + (size_t)s * EE];
        float d = 0.f;
#pragma unroll
        for (int e = 0; e < HS; e++) d = fmaf(qs[e], kr[e], d);
        d *= scale;
        sc[s] = d;
        lmax = fmaxf(lmax, d);
    }
    red[tid] = lmax; __syncthreads();
    for (int o = 64; o > 0; o >>= 1) {
        if (tid < o) red[tid] = fmaxf(red[tid], red[tid + o]);
        __syncthreads();
    }
    const float m = red[0];
    __syncthreads();

    float lsum = 0.f;
    for (int s = tid; s <= tq; s += 128) {
        float p = expf(sc[s] - m);
        sc[s] = p;
        lsum += p;
    }
    red[tid] = lsum; __syncthreads();
    for (int o = 64; o > 0; o >>= 1) {
        if (tid < o) red[tid] += red[tid + o];
        __syncthreads();
    }
    const float inv = 1.f / red[0];

    for (int d0 = tid; d0 < HS; d0 += 128) {
        float acc = 0.f;
        for (int s = 0; s <= tq; s++)
            acc = fmaf(sc[s], v[base + (size_t)s * EE + d0], acc);
        out[base + (size_t)tq * EE + d0] = acc * inv;
    }
}

// ---------------- loss ----------------
__global__ void loss_zero_kernel(float* loss) { *loss = 0.f; }

__global__ void loss_kernel(const float* __restrict__ logits,
                            const int* __restrict__ targets,
                            float* __restrict__ loss)
{
    const int row = blockIdx.x;
    const int tid = threadIdx.x;   // 256
    const float* lr = logits + (size_t)row * VV;

    __shared__ float red[256];
    float lmax = -1e30f;
    for (int j = tid; j < VV; j += 256) lmax = fmaxf(lmax, lr[j]);
    red[tid] = lmax; __syncthreads();
    for (int o = 128; o > 0; o >>= 1) {
        if (tid < o) red[tid] = fmaxf(red[tid], red[tid + o]);
        __syncthreads();
    }
    const float m = red[0];
    __syncthreads();

    float lsum = 0.f;
    for (int j = tid; j < VV; j += 256) lsum += expf(lr[j] - m);
    red[tid] = lsum; __syncthreads();
    for (int o = 128; o > 0; o >>= 1) {
        if (tid < o) red[tid] += red[tid + o];
        __syncthreads();
    }
    if (tid == 0) {
        float lp = lr[targets[row]] - m - logf(red[0]);
        atomicAdd(loss, -lp * (1.f / (float)MM));
    }
}

// ---------------- launch ----------------
extern "C" void kernel_launch(void* const* d_in, const int* in_sizes, int n_in,
                              void* d_out, int out_size)
{
    const int*   idx     = (const int*)  d_in[0];
    const int*   targets = (const int*)  d_in[1];
    const float* tok     = (const float*)d_in[2];
    const float* pos     = (const float*)d_in[3];
    const float* Wq      = (const float*)d_in[4];
    const float* Wk      = (const float*)d_in[5];
    const float* Wv      = (const float*)d_in[6];
    const float* Wo      = (const float*)d_in[7];
    const float* bo      = (const float*)d_in[8];
    const float* ln1_g   = (const float*)d_in[9];
    const float* ln1_b   = (const float*)d_in[10];
    const float* ln2_g   = (const float*)d_in[11];
    const float* ln2_b   = (const float*)d_in[12];
    const float* W1      = (const float*)d_in[13];
    const float* b1      = (const float*)d_in[14];
    const float* W2      = (const float*)d_in[15];
    const float* b2      = (const float*)d_in[16];
    const float* lnf_g   = (const float*)d_in[17];
    const float* lnf_b   = (const float*)d_in[18];

    float *x, *xn, *q, *k, *v, *att, *h4, *lg_scratch;
    cudaGetSymbolAddress((void**)&x,   g_x);
    cudaGetSymbolAddress((void**)&xn,  g_xn);
    cudaGetSymbolAddress((void**)&q,   g_q);
    cudaGetSymbolAddress((void**)&k,   g_k);
    cudaGetSymbolAddress((void**)&v,   g_v);
    cudaGetSymbolAddress((void**)&att, g_att);
    cudaGetSymbolAddress((void**)&h4,  g_h4);
    cudaGetSymbolAddress((void**)&lg_scratch, g_logits_scratch);

    const bool out_holds_logits = ((long long)out_size >= (long long)MM * VV);
    float* logits = out_holds_logits ? (float*)d_out : lg_scratch;

    // embedding
    {
        size_t n = (size_t)MM * EE;
        embed_kernel<<<(unsigned)((n + 255) / 256), 256>>>(idx, tok, pos, x);
    }

    const dim3 gE(EE / 128, MM / 128);   // N=768
    const dim3 gF(FF / 128, MM / 128);   // N=3072
    const dim3 gV(VV / 128, MM / 128);   // N=32000

    for (int l = 0; l < LL; l++) {
        const size_t oEE = (size_t)l * EE * EE;
        ln_kernel<<<MM, 256>>>(x, ln1_g + (size_t)l * EE, ln1_b + (size_t)l * EE, xn);
        gemm_kernel<false, false><<<gE, 256>>>(xn, Wq + oEE, nullptr, nullptr, q, MM, EE, EE);
        gemm_kernel<false, false><<<gE, 256>>>(xn, Wk + oEE, nullptr, nullptr, k, MM, EE, EE);
        gemm_kernel<false, false><<<gE, 256>>>(xn, Wv + oEE, nullptr, nullptr, v, MM, EE, EE);
        attn_kernel<<<dim3(TT, HH, BB), 128>>>(q, k, v, att);
        // x = x + att @ Wo + bo   (residual fused, in-place safe: 1 writer per element)
        gemm_kernel<false, false><<<gE, 256>>>(att, Wo + oEE, bo + (size_t)l * EE, x, x, MM, EE, EE);

        ln_kernel<<<MM, 256>>>(x, ln2_g + (size_t)l * EE, ln2_b + (size_t)l * EE, xn);
        gemm_kernel<false, true ><<<gF, 256>>>(xn, W1 + (size_t)l * EE * FF,
                                               b1 + (size_t)l * FF, nullptr, h4, MM, FF, EE);
        gemm_kernel<false, false><<<gE, 256>>>(h4, W2 + (size_t)l * FF * EE,
                                               b2 + (size_t)l * EE, x, x, MM, EE, FF);
    }

    ln_kernel<<<MM, 256>>>(x, lnf_g, lnf_b, xn);
    // logits = xn @ tok^T  (tied head, NT)
    gemm_kernel<true, false><<<gV, 256>>>(xn, tok, nullptr, nullptr, logits, MM, VV, EE);

    // loss -> last element of d_out (after logits) or d_out[0] if out is just the loss
    float* loss_ptr = out_holds_logits ? ((float*)d_out + (size_t)MM * VV)
                                       : (float*)d_out;
    if (!out_holds_logits || (long long)out_size > (long long)MM * VV) {
        loss_zero_kernel<<<1, 1>>>(loss_ptr);
        loss_kernel<<<MM, 256>>>(logits, targets, loss_ptr);
    }
}

// round 4
// speedup vs baseline: 4.3527x; 4.3524x over previous
#include <cuda_runtime.h>
#include <cuda_bf16.h>
#include <math.h>
#include <stdint.h>

// ---------------- problem constants ----------------
#define BB 4
#define TT 1024
#define EE 768
#define HH 8
#define HS 96
#define LL 8
#define VV 32000
#define FF 3072            // 4*E
#define MM (BB*TT)         // 4096 rows
#define E3 (3*EE)          // 2304 (split-K for E)
#define F3 (3*FF)          // 9216 (split-K for 4E)

typedef __nv_bfloat16 bf16;

// ---------------- scratch (device globals; no allocation allowed) ----------------
__device__ __align__(256) float g_x   [(size_t)MM*EE];
__device__ __align__(256) bf16  g_xn2 [(size_t)MM*E3];
__device__ __align__(256) float g_qkv [(size_t)MM*E3];
__device__ __align__(256) bf16  g_att2[(size_t)MM*E3];
__device__ __align__(256) bf16  g_h42 [(size_t)MM*F3];

__device__ __align__(256) bf16  g_wqkv2[(size_t)LL*E3*E3];     // [l][3K=2304][N=2304]
__device__ __align__(256) bf16  g_wo2  [(size_t)LL*E3*EE];     // [l][2304][768]
__device__ __align__(256) bf16  g_w12  [(size_t)LL*E3*FF];     // [l][2304][3072]
__device__ __align__(256) bf16  g_w22  [(size_t)LL*F3*EE];     // [l][9216][768]
__device__ __align__(256) bf16  g_tok2 [(size_t)E3*VV];        // [2304][32000] (tok^T split)

__device__ __align__(256) float g_logits_scratch[(size_t)MM*VV];

// ---------------- helpers ----------------
__device__ __forceinline__ void split2(float v, bf16& hi, bf16& lo) {
    hi = __float2bfloat16(v);
    lo = __float2bfloat16(v - __bfloat162float(hi));
}

__device__ __forceinline__ void cp16(void* dst_smem, const void* src_gmem) {
    uint32_t s = (uint32_t)__cvta_generic_to_shared(dst_smem);
    asm volatile("cp.async.cg.shared.global [%0], [%1], 16;\n" :: "r"(s), "l"(src_gmem));
}
__device__ __forceinline__ void cp_commit() { asm volatile("cp.async.commit_group;\n" ::: "memory"); }
__device__ __forceinline__ void cp_wait1()  { asm volatile("cp.async.wait_group 1;\n" ::: "memory"); }

__device__ __forceinline__ void ldmA4(uint32_t* a, const void* p) {
    uint32_t s = (uint32_t)__cvta_generic_to_shared(p);
    asm volatile("ldmatrix.sync.aligned.m8n8.x4.shared.b16 {%0,%1,%2,%3}, [%4];"
                 : "=r"(a[0]), "=r"(a[1]), "=r"(a[2]), "=r"(a[3]) : "r"(s));
}
__device__ __forceinline__ void ldmB2t(uint32_t* b, const void* p) {
    uint32_t s = (uint32_t)__cvta_generic_to_shared(p);
    asm volatile("ldmatrix.sync.aligned.m8n8.x2.trans.shared.b16 {%0,%1}, [%2];"
                 : "=r"(b[0]), "=r"(b[1]) : "r"(s));
}
__device__ __forceinline__ void mma16816(float* c, const uint32_t* a, const uint32_t* b) {
    asm volatile(
        "mma.sync.aligned.m16n8k16.row.col.f32.bf16.bf16.f32 "
        "{%0,%1,%2,%3},{%4,%5,%6,%7},{%8,%9},{%0,%1,%2,%3};"
        : "+f"(c[0]), "+f"(c[1]), "+f"(c[2]), "+f"(c[3])
        : "r"(a[0]), "r"(a[1]), "r"(a[2]), "r"(a[3]), "r"(b[0]), "r"(b[1]));
}

// ---------------- embedding ----------------
__global__ void embed_kernel(const int* __restrict__ idx,
                             const float* __restrict__ tok,
                             const float* __restrict__ pos,
                             float* __restrict__ x)
{
    size_t i = (size_t)blockIdx.x * blockDim.x + threadIdx.x;
    if (i >= (size_t)MM * EE) return;
    int e  = (int)(i % EE);
    int bt = (int)(i / EE);
    int t  = bt % TT;
    x[i] = tok[(size_t)idx[bt] * EE + e] + pos[(size_t)t * EE + e];
}

// ---------------- layernorm -> split bf16 [row, 3E]  (A-side: [hi | hi | lo]) ----------------
__global__ void ln_split_kernel(const float* __restrict__ x,
                                const float* __restrict__ g,
                                const float* __restrict__ b,
                                bf16* __restrict__ out)
{
    int row = blockIdx.x;
    int tid = threadIdx.x;  // 256
    const float* xr = x + (size_t)row * EE;
    float s = 0.f, s2 = 0.f;
    for (int e = tid; e < EE; e += 256) { float v = xr[e]; s += v; s2 += v * v; }
    __shared__ float r1[256], r2[256];
    r1[tid] = s; r2[tid] = s2; __syncthreads();
    for (int o = 128; o > 0; o >>= 1) {
        if (tid < o) { r1[tid] += r1[tid + o]; r2[tid] += r2[tid + o]; }
        __syncthreads();
    }
    float mean = r1[0] * (1.f / EE);
    float var  = r2[0] * (1.f / EE) - mean * mean;
    float inv  = rsqrtf(var + 1e-5f);
    bf16* orow = out + (size_t)row * E3;
    for (int e = tid; e < EE; e += 256) {
        float v = (xr[e] - mean) * inv * g[e] + b[e];
        bf16 hi, lo; split2(v, hi, lo);
        orow[e] = hi; orow[EE + e] = hi; orow[2*EE + e] = lo;
    }
}

// ---------------- weight conversion: W[K,N] fp32 -> B-side rows [hi; lo; hi] ----------------
__global__ void convert_w_kernel(const float* __restrict__ W, bf16* __restrict__ out,
                                 int K, int N, int pitch, int colOff)
{
    int i = blockIdx.x * 256 + threadIdx.x;
    if (i >= K * N) return;
    int k = i / N, n = i % N;
    float v = W[i];
    bf16 hi, lo; split2(v, hi, lo);
    out[(size_t)k * pitch + colOff + n]           = hi;
    out[(size_t)(K + k) * pitch + colOff + n]     = lo;
    out[(size_t)(2 * K + k) * pitch + colOff + n] = hi;
}

// Contract: A segments [hi | hi | lo], B rows [hi; lo; hi]
//   seg0: Ahi*Bhi, seg1: Ahi*Blo, seg2: Alo*Bhi   (lo*lo dropped, ~2^-18)

// ---------------- tok transpose + split: out[3E, V] from tok[V, E] (B-side) ----------------
__global__ void convert_tok_kernel(const float* __restrict__ tok, bf16* __restrict__ out)
{
    __shared__ float t[32][33];
    int k0 = blockIdx.x * 32, n0 = blockIdx.y * 32;
    int tx = threadIdx.x, ty = threadIdx.y;
    t[ty][tx] = tok[(size_t)(n0 + ty) * EE + k0 + tx];
    __syncthreads();
    float v = t[tx][ty];   // = tok[n0+tx][k0+ty]
    bf16 hi, lo; split2(v, hi, lo);
    size_t k = k0 + ty, n = n0 + tx;
    out[k * VV + n]              = hi;
    out[(EE + k) * VV + n]       = lo;
    out[(2*EE + k) * VV + n]     = hi;
}

// ---------------- tensor-core GEMM: C[M,N] = A[M,K2] @ B[K2,N] ----------------
// A, B bf16. Epilogue: (+bias) (+GELU) (+res) ; output fp32 C (SPLIT=false)
// or A-side split bf16 [M, 3N] (SPLIT=true, feeds the next GEMM as A => [hi|hi|lo]).
// M mult of 128, N mult of 128, K2 mult of 32.
template<bool GELU, bool SPLIT>
__global__ void __launch_bounds__(256)
mma_gemm(const bf16* __restrict__ A, const bf16* __restrict__ B,
         const float* __restrict__ bias, const float* __restrict__ res,
         void* __restrict__ Cv, int M, int N, int K2)
{
    __shared__ bf16 As[2][128 * 40];   // pitch 40 (pad 8)
    __shared__ bf16 Bs[2][32 * 144];   // pitch 144 (pad 16)

    const int tid  = threadIdx.x;
    const int lane = tid & 31;
    const int warp = tid >> 5;
    const int wm   = warp & 1;         // 0..1 -> 64-row slab
    const int wn   = warp >> 1;        // 0..3 -> 32-col slab
    const int row0 = blockIdx.y * 128;
    const int col0 = blockIdx.x * 128;

    float acc[4][4][4];
#pragma unroll
    for (int i = 0; i < 4; i++)
#pragma unroll
        for (int j = 0; j < 4; j++)
#pragma unroll
            for (int r = 0; r < 4; r++) acc[i][j][r] = 0.f;

    const int ntiles = K2 >> 5;

    auto load_tile = [&](int s, int k0) {
#pragma unroll
        for (int i = 0; i < 2; i++) {
            int idx = tid + i * 256;
            int r = idx >> 2, c = (idx & 3) * 8;
            cp16(&As[s][r * 40 + c], &A[(size_t)(row0 + r) * K2 + k0 + c]);
        }
#pragma unroll
        for (int i = 0; i < 2; i++) {
            int idx = tid + i * 256;
            int r = idx >> 4, c = (idx & 15) * 8;
            cp16(&Bs[s][r * 144 + c], &B[(size_t)(k0 + r) * N + col0 + c]);
        }
    };

    load_tile(0, 0);
    cp_commit();

    for (int t = 0; t < ntiles; t++) {
        if (t + 1 < ntiles) load_tile((t + 1) & 1, (t + 1) * 32);
        cp_commit();
        cp_wait1();
        __syncthreads();
        const int s = t & 1;

#pragma unroll
        for (int kk = 0; kk < 32; kk += 16) {
            uint32_t a[4][4], b[4][2];
#pragma unroll
            for (int mi = 0; mi < 4; mi++)
                ldmA4(a[mi], &As[s][(wm * 64 + mi * 16 + (lane & 15)) * 40 + kk + (lane >> 4) * 8]);
#pragma unroll
            for (int ni = 0; ni < 4; ni++)
                ldmB2t(b[ni], &Bs[s][(kk + (lane & 15)) * 144 + wn * 32 + ni * 8]);
#pragma unroll
            for (int mi = 0; mi < 4; mi++)
#pragma unroll
                for (int ni = 0; ni < 4; ni++)
                    mma16816(acc[mi][ni], a[mi], b[ni]);
        }
        __syncthreads();
    }

    // ---- epilogue ----
    const int gid = lane >> 2, tig = lane & 3;
#pragma unroll
    for (int mi = 0; mi < 4; mi++) {
#pragma unroll
        for (int ni = 0; ni < 4; ni++) {
            int gr = row0 + wm * 64 + mi * 16 + gid;
            int gc = col0 + wn * 32 + ni * 8 + tig * 2;
#pragma unroll
            for (int half = 0; half < 2; half++) {
                int r = gr + half * 8;
#pragma unroll
                for (int cc = 0; cc < 2; cc++) {
                    float c = acc[mi][ni][half * 2 + cc];
                    int col = gc + cc;
                    if (bias) c += bias[col];
                    if (GELU) c = 0.5f * c * (1.f + erff(c * 0.70710678118654752f));
                    if (SPLIT) {
                        // A-side layout for the consumer GEMM: [hi | hi | lo]
                        bf16 hi, lo; split2(c, hi, lo);
                        bf16* C = (bf16*)Cv;
                        size_t base = (size_t)r * (3 * N) + col;
                        C[base] = hi; C[base + N] = hi; C[base + 2 * N] = lo;
                    } else {
                        float* C = (float*)Cv;
                        if (res) c += res[(size_t)r * N + col];
                        C[(size_t)r * N + col] = c;
                    }
                }
            }
        }
    }
}

// ---------------- flash-style attention ----------------
// qkv: [M, 2304] fp32 (cols: q | k | v, each [H=8][HS=96]).
// out: att2 A-side split bf16 [M, 3*768].
__global__ void __launch_bounds__(128)
attn_kernel(const float* __restrict__ qkv, bf16* __restrict__ att2)
{
    const int tq0  = blockIdx.x * 32;
    const int h    = blockIdx.y;
    const int b    = blockIdx.z;
    const int tid  = threadIdx.x;
    const int lane = tid & 31;
    const int warp = tid >> 5;

    __shared__ float qs[32][96];
    __shared__ float ks[96][33];
    __shared__ float vs[32][96];

    const size_t rowbase = (size_t)(b * TT) * E3;
    const int qoff = h * HS, koff = EE + h * HS, voff = 2 * EE + h * HS;
    const float scale = 0.10206207261596577f;   // 96^-0.5

    for (int i = tid; i < 32 * 96; i += 128) {
        int r = i / 96, e = i % 96;
        qs[r][e] = qkv[rowbase + (size_t)(tq0 + r) * E3 + qoff + e] * scale;
    }

    float mq[8], lq[8], acc[8][3];
#pragma unroll
    for (int q = 0; q < 8; q++) {
        mq[q] = -1e30f; lq[q] = 0.f;
        acc[q][0] = acc[q][1] = acc[q][2] = 0.f;
    }
    const int tqw0 = tq0 + warp * 8;

    for (int c0 = 0; c0 <= tq0 + 31; c0 += 32) {
        __syncthreads();
        for (int i = tid; i < 32 * 96; i += 128) {
            int key = i / 96, e = i % 96;
            float kv = qkv[rowbase + (size_t)(c0 + key) * E3 + koff + e];
            ks[e][key] = kv;
            vs[key][e] = qkv[rowbase + (size_t)(c0 + key) * E3 + voff + e];
        }
        __syncthreads();

#pragma unroll
        for (int q = 0; q < 8; q++) {
            const int tqg = tqw0 + q;
            if (c0 > tqg) continue;
            const float* qr = qs[warp * 8 + q];
            float s = 0.f;
#pragma unroll
            for (int e = 0; e < 96; e++) s = fmaf(qr[e], ks[e][lane], s);
            if (c0 + lane > tqg) s = -1e30f;

            float mn = s;
#pragma unroll
            for (int o = 16; o > 0; o >>= 1) mn = fmaxf(mn, __shfl_xor_sync(0xffffffffu, mn, o));
            float mnew  = fmaxf(mq[q], mn);
            float alpha = __expf(mq[q] - mnew);
            float p     = __expf(s - mnew);
            float ps = p;
#pragma unroll
            for (int o = 16; o > 0; o >>= 1) ps += __shfl_xor_sync(0xffffffffu, ps, o);
            lq[q] = lq[q] * alpha + ps;
            mq[q] = mnew;
            acc[q][0] *= alpha; acc[q][1] *= alpha; acc[q][2] *= alpha;
#pragma unroll
            for (int k2 = 0; k2 < 32; k2++) {
                float pk = __shfl_sync(0xffffffffu, p, k2);
                acc[q][0] = fmaf(pk, vs[k2][lane],      acc[q][0]);
                acc[q][1] = fmaf(pk, vs[k2][lane + 32], acc[q][1]);
                acc[q][2] = fmaf(pk, vs[k2][lane + 64], acc[q][2]);
            }
        }
    }

    // epilogue: write A-side split bf16 into att2 (cols h*96 + d): [hi | hi | lo]
#pragma unroll
    for (int q = 0; q < 8; q++) {
        const int tqg = tqw0 + q;
        const float inv = 1.f / lq[q];
        const size_t orow = (size_t)(b * TT + tqg) * E3;
#pragma unroll
        for (int j = 0; j < 3; j++) {
            int d = h * HS + lane + j * 32;
            float v = acc[q][j] * inv;
            bf16 hi, lo; split2(v, hi, lo);
            att2[orow + d]          = hi;
            att2[orow + EE + d]     = hi;
            att2[orow + 2 * EE + d] = lo;
        }
    }
}

// ---------------- loss ----------------
__global__ void loss_zero_kernel(float* loss) { *loss = 0.f; }

__global__ void loss_kernel(const float* __restrict__ logits,
                            const int* __restrict__ targets,
                            float* __restrict__ loss)
{
    const int row = blockIdx.x;
    const int tid = threadIdx.x;   // 256
    const float* lr = logits + (size_t)row * VV;

    __shared__ float red[256];
    float lmax = -1e30f;
    for (int j = tid; j < VV; j += 256) lmax = fmaxf(lmax, lr[j]);
    red[tid] = lmax; __syncthreads();
    for (int o = 128; o > 0; o >>= 1) {
        if (tid < o) red[tid] = fmaxf(red[tid], red[tid + o]);
        __syncthreads();
    }
    const float m = red[0];
    __syncthreads();

    float lsum = 0.f;
    for (int j = tid; j < VV; j += 256) lsum += expf(lr[j] - m);
    red[tid] = lsum; __syncthreads();
    for (int o = 128; o > 0; o >>= 1) {
        if (tid < o) red[tid] += red[tid + o];
        __syncthreads();
    }
    if (tid == 0) {
        float lp = lr[targets[row]] - m - logf(red[0]);
        atomicAdd(loss, -lp * (1.f / (float)MM));
    }
}

// ---------------- launch ----------------
extern "C" void kernel_launch(void* const* d_in, const int* in_sizes, int n_in,
                              void* d_out, int out_size)
{
    const int*   idx     = (const int*)  d_in[0];
    const int*   targets = (const int*)  d_in[1];
    const float* tok     = (const float*)d_in[2];
    const float* pos     = (const float*)d_in[3];
    const float* Wq      = (const float*)d_in[4];
    const float* Wk      = (const float*)d_in[5];
    const float* Wv      = (const float*)d_in[6];
    const float* Wo      = (const float*)d_in[7];
    const float* bo      = (const float*)d_in[8];
    const float* ln1_g   = (const float*)d_in[9];
    const float* ln1_b   = (const float*)d_in[10];
    const float* ln2_g   = (const float*)d_in[11];
    const float* ln2_b   = (const float*)d_in[12];
    const float* W1      = (const float*)d_in[13];
    const float* b1      = (const float*)d_in[14];
    const float* W2      = (const float*)d_in[15];
    const float* b2      = (const float*)d_in[16];
    const float* lnf_g   = (const float*)d_in[17];
    const float* lnf_b   = (const float*)d_in[18];

    float *x, *qkv, *lg_scratch;
    bf16 *xn2, *att2, *h42, *wqkv2, *wo2, *w12, *w22, *tok2;
    cudaGetSymbolAddress((void**)&x,    g_x);
    cudaGetSymbolAddress((void**)&xn2,  g_xn2);
    cudaGetSymbolAddress((void**)&qkv,  g_qkv);
    cudaGetSymbolAddress((void**)&att2, g_att2);
    cudaGetSymbolAddress((void**)&h42,  g_h42);
    cudaGetSymbolAddress((void**)&wqkv2,g_wqkv2);
    cudaGetSymbolAddress((void**)&wo2,  g_wo2);
    cudaGetSymbolAddress((void**)&w12,  g_w12);
    cudaGetSymbolAddress((void**)&w22,  g_w22);
    cudaGetSymbolAddress((void**)&tok2, g_tok2);
    cudaGetSymbolAddress((void**)&lg_scratch, g_logits_scratch);

    const bool out_holds_logits = ((long long)out_size >= (long long)MM * VV);
    float* logits = out_holds_logits ? (float*)d_out : lg_scratch;

    // ---- weight conversions (every call; deterministic) ----
    {
        const int gEE = (EE * EE + 255) / 256;
        const int gEF = (EE * FF + 255) / 256;
        const int gFE = (FF * EE + 255) / 256;
        for (int l = 0; l < LL; l++) {
            const size_t oEE = (size_t)l * EE * EE;
            bf16* wq2l = wqkv2 + (size_t)l * E3 * E3;
            convert_w_kernel<<<gEE, 256>>>(Wq + oEE, wq2l, EE, EE, E3, 0);
            convert_w_kernel<<<gEE, 256>>>(Wk + oEE, wq2l, EE, EE, E3, EE);
            convert_w_kernel<<<gEE, 256>>>(Wv + oEE, wq2l, EE, EE, E3, 2 * EE);
            convert_w_kernel<<<gEE, 256>>>(Wo + oEE, wo2 + (size_t)l * E3 * EE, EE, EE, EE, 0);
            convert_w_kernel<<<gEF, 256>>>(W1 + (size_t)l * EE * FF, w12 + (size_t)l * E3 * FF, EE, FF, FF, 0);
            convert_w_kernel<<<gFE, 256>>>(W2 + (size_t)l * FF * EE, w22 + (size_t)l * F3 * EE, FF, EE, EE, 0);
        }
        convert_tok_kernel<<<dim3(EE / 32, VV / 32), dim3(32, 32)>>>(tok, tok2);
    }

    // ---- embedding ----
    {
        size_t n = (size_t)MM * EE;
        embed_kernel<<<(unsigned)((n + 255) / 256), 256>>>(idx, tok, pos, x);
    }

    const dim3 gQKV(E3 / 128, MM / 128);
    const dim3 gE  (EE / 128, MM / 128);
    const dim3 gF  (FF / 128, MM / 128);
    const dim3 gV  (VV / 128, MM / 128);

    for (int l = 0; l < LL; l++) {
        ln_split_kernel<<<MM, 256>>>(x, ln1_g + (size_t)l * EE, ln1_b + (size_t)l * EE, xn2);
        mma_gemm<false, false><<<gQKV, 256>>>(xn2, wqkv2 + (size_t)l * E3 * E3,
                                              nullptr, nullptr, qkv, MM, E3, E3);
        attn_kernel<<<dim3(TT / 32, HH, BB), 128>>>(qkv, att2);
        mma_gemm<false, false><<<gE, 256>>>(att2, wo2 + (size_t)l * E3 * EE,
                                            bo + (size_t)l * EE, x, x, MM, EE, E3);
        ln_split_kernel<<<MM, 256>>>(x, ln2_g + (size_t)l * EE, ln2_b + (size_t)l * EE, xn2);
        mma_gemm<true, true><<<gF, 256>>>(xn2, w12 + (size_t)l * E3 * FF,
                                          b1 + (size_t)l * FF, nullptr, h42, MM, FF, E3);
        mma_gemm<false, false><<<gE, 256>>>(h42, w22 + (size_t)l * F3 * EE,
                                            b2 + (size_t)l * EE, x, x, MM, EE, F3);
    }

    ln_split_kernel<<<MM, 256>>>(x, lnf_g, lnf_b, xn2);
    mma_gemm<false, false><<<gV, 256>>>(xn2, tok2, nullptr, nullptr, logits, MM, VV, E3);

    float* loss_ptr = out_holds_logits ? ((float*)d_out + (size_t)MM * VV)
                                       : (float*)d_out;
    if (!out_holds_logits || (long long)out_size > (long long)MM * VV) {
        loss_zero_kernel<<<1, 1>>>(loss_ptr);
        loss_kernel<<<MM, 256>>>(logits, targets, loss_ptr);
    }
}

// round 5
// speedup vs baseline: 6.3412x; 1.4569x over previous
#include <cuda_runtime.h>
#include <cuda_bf16.h>
#include <math.h>
#include <stdint.h>

// ---------------- problem constants ----------------
#define BB 4
#define TT 1024
#define EE 768
#define HH 8
#define HS 96
#define LL 8
#define VV 32000
#define FF 3072            // 4*E
#define MM (BB*TT)         // 4096 rows
#define E3 (3*EE)          // 2304 (split-K for E)
#define F3 (3*FF)          // 9216 (split-K for 4E)

typedef __nv_bfloat16 bf16;

// ---------------- scratch (device globals; no allocation allowed) ----------------
__device__ __align__(256) float g_x   [(size_t)MM*EE];
__device__ __align__(256) bf16  g_xn2 [(size_t)MM*E3];
__device__ __align__(256) bf16  g_qkv2[(size_t)MM*3*E3];       // QKV GEMM split output [M][3*2304]
__device__ __align__(256) bf16  g_att2[(size_t)MM*E3];
__device__ __align__(256) bf16  g_h42 [(size_t)MM*F3];

__device__ __align__(256) bf16  g_wqkv2[(size_t)LL*E3*E3];     // [l][3K=2304][N=2304]
__device__ __align__(256) bf16  g_wo2  [(size_t)LL*E3*EE];
__device__ __align__(256) bf16  g_w12  [(size_t)LL*E3*FF];
__device__ __align__(256) bf16  g_w22  [(size_t)LL*F3*EE];
__device__ __align__(256) bf16  g_tok2 [(size_t)E3*VV];

__device__ __align__(256) float g_logits_scratch[(size_t)MM*VV];

// ---------------- helpers ----------------
__device__ __forceinline__ void split2(float v, bf16& hi, bf16& lo) {
    hi = __float2bfloat16(v);
    lo = __float2bfloat16(v - __bfloat162float(hi));
}
__device__ __forceinline__ uint32_t pack2(bf16 a, bf16 b) {
    uint16_t x = *(uint16_t*)&a, y = *(uint16_t*)&b;
    return (uint32_t)x | ((uint32_t)y << 16);
}

__device__ __forceinline__ void cp16(void* dst_smem, const void* src_gmem) {
    uint32_t s = (uint32_t)__cvta_generic_to_shared(dst_smem);
    asm volatile("cp.async.cg.shared.global [%0], [%1], 16;\n" :: "r"(s), "l"(src_gmem));
}
__device__ __forceinline__ void cp_commit() { asm volatile("cp.async.commit_group;\n" ::: "memory"); }
__device__ __forceinline__ void cp_wait1()  { asm volatile("cp.async.wait_group 1;\n" ::: "memory"); }

__device__ __forceinline__ void ldmA4(uint32_t* a, const void* p) {
    uint32_t s = (uint32_t)__cvta_generic_to_shared(p);
    asm volatile("ldmatrix.sync.aligned.m8n8.x4.shared.b16 {%0,%1,%2,%3}, [%4];"
                 : "=r"(a[0]), "=r"(a[1]), "=r"(a[2]), "=r"(a[3]) : "r"(s));
}
__device__ __forceinline__ void ldmB2t(uint32_t* b, const void* p) {
    uint32_t s = (uint32_t)__cvta_generic_to_shared(p);
    asm volatile("ldmatrix.sync.aligned.m8n8.x2.trans.shared.b16 {%0,%1}, [%2];"
                 : "=r"(b[0]), "=r"(b[1]) : "r"(s));
}
__device__ __forceinline__ void ldmB4t(uint32_t* b, const void* p) {
    uint32_t s = (uint32_t)__cvta_generic_to_shared(p);
    asm volatile("ldmatrix.sync.aligned.m8n8.x4.trans.shared.b16 {%0,%1,%2,%3}, [%4];"
                 : "=r"(b[0]), "=r"(b[1]), "=r"(b[2]), "=r"(b[3]) : "r"(s));
}
__device__ __forceinline__ void mma16816(float* c, const uint32_t* a, const uint32_t* b) {
    asm volatile(
        "mma.sync.aligned.m16n8k16.row.col.f32.bf16.bf16.f32 "
        "{%0,%1,%2,%3},{%4,%5,%6,%7},{%8,%9},{%0,%1,%2,%3};"
        : "+f"(c[0]), "+f"(c[1]), "+f"(c[2]), "+f"(c[3])
        : "r"(a[0]), "r"(a[1]), "r"(a[2]), "r"(a[3]), "r"(b[0]), "r"(b[1]));
}

// ---------------- embedding ----------------
__global__ void embed_kernel(const int* __restrict__ idx,
                             const float* __restrict__ tok,
                             const float* __restrict__ pos,
                             float* __restrict__ x)
{
    size_t i = (size_t)blockIdx.x * blockDim.x + threadIdx.x;
    if (i >= (size_t)MM * EE) return;
    int e  = (int)(i % EE);
    int bt = (int)(i / EE);
    int t  = bt % TT;
    x[i] = tok[(size_t)idx[bt] * EE + e] + pos[(size_t)t * EE + e];
}

// ---------------- layernorm -> A-side split bf16 [row, 3E]: [hi | hi | lo] ----------------
__global__ void ln_split_kernel(const float* __restrict__ x,
                                const float* __restrict__ g,
                                const float* __restrict__ b,
                                bf16* __restrict__ out)
{
    int row = blockIdx.x;
    int tid = threadIdx.x;  // 256
    const float* xr = x + (size_t)row * EE;
    float s = 0.f, s2 = 0.f;
    for (int e = tid; e < EE; e += 256) { float v = xr[e]; s += v; s2 += v * v; }
    __shared__ float r1[256], r2[256];
    r1[tid] = s; r2[tid] = s2; __syncthreads();
    for (int o = 128; o > 0; o >>= 1) {
        if (tid < o) { r1[tid] += r1[tid + o]; r2[tid] += r2[tid + o]; }
        __syncthreads();
    }
    float mean = r1[0] * (1.f / EE);
    float var  = r2[0] * (1.f / EE) - mean * mean;
    float inv  = rsqrtf(var + 1e-5f);
    bf16* orow = out + (size_t)row * E3;
    for (int e = tid; e < EE; e += 256) {
        float v = (xr[e] - mean) * inv * g[e] + b[e];
        bf16 hi, lo; split2(v, hi, lo);
        orow[e] = hi; orow[EE + e] = hi; orow[2*EE + e] = lo;
    }
}

// ---------------- weight conversion: W[K,N] fp32 -> B-side rows [hi; lo; hi] ----------------
__global__ void convert_w_kernel(const float* __restrict__ W, bf16* __restrict__ out,
                                 int K, int N, int pitch, int colOff)
{
    int i = blockIdx.x * 256 + threadIdx.x;
    if (i >= K * N) return;
    int k = i / N, n = i % N;
    float v = W[i];
    bf16 hi, lo; split2(v, hi, lo);
    out[(size_t)k * pitch + colOff + n]           = hi;
    out[(size_t)(K + k) * pitch + colOff + n]     = lo;
    out[(size_t)(2 * K + k) * pitch + colOff + n] = hi;
}

// Contract: A segments [hi | hi | lo], B rows [hi; lo; hi]
//   seg0: Ahi*Bhi, seg1: Ahi*Blo, seg2: Alo*Bhi   (lo*lo dropped, ~2^-18)

// ---------------- tok transpose + split: out[3E, V] from tok[V, E] (B-side) ----------------
__global__ void convert_tok_kernel(const float* __restrict__ tok, bf16* __restrict__ out)
{
    __shared__ float t[32][33];
    int k0 = blockIdx.x * 32, n0 = blockIdx.y * 32;
    int tx = threadIdx.x, ty = threadIdx.y;
    t[ty][tx] = tok[(size_t)(n0 + ty) * EE + k0 + tx];
    __syncthreads();
    float v = t[tx][ty];
    bf16 hi, lo; split2(v, hi, lo);
    size_t k = k0 + ty, n = n0 + tx;
    out[k * VV + n]              = hi;
    out[(EE + k) * VV + n]       = lo;
    out[(2*EE + k) * VV + n]     = hi;
}

// ---------------- tensor-core GEMM: C[M,N] = A[M,K2] @ B[K2,N] ----------------
// K-tile 64, 2-stage cp.async. Dynamic smem = 73728 B.
template<bool GELU, bool SPLIT>
__global__ void __launch_bounds__(256)
mma_gemm(const bf16* __restrict__ A, const bf16* __restrict__ B,
         const float* __restrict__ bias, const float* __restrict__ res,
         void* __restrict__ Cv, int M, int N, int K2)
{
    extern __shared__ char dynsm[];
    bf16* As = (bf16*)dynsm;            // [2][128*72]  (pitch 72)
    bf16* Bs = (bf16*)dynsm + 18432;    // [2][64*144]  (pitch 144)

    const int tid  = threadIdx.x;
    const int lane = tid & 31;
    const int warp = tid >> 5;
    const int wm   = warp & 1;
    const int wn   = warp >> 1;
    const int row0 = blockIdx.y * 128;
    const int col0 = blockIdx.x * 128;

    float acc[4][4][4];
#pragma unroll
    for (int i = 0; i < 4; i++)
#pragma unroll
        for (int j = 0; j < 4; j++)
#pragma unroll
            for (int r = 0; r < 4; r++) acc[i][j][r] = 0.f;

    const int ntiles = K2 >> 6;

    auto load_tile = [&](int s, int k0) {
#pragma unroll
        for (int i = 0; i < 4; i++) {
            int idx = tid + i * 256;
            int r = idx >> 3, c = (idx & 7) * 8;
            cp16(&As[s * 9216 + r * 72 + c], &A[(size_t)(row0 + r) * K2 + k0 + c]);
        }
#pragma unroll
        for (int i = 0; i < 4; i++) {
            int idx = tid + i * 256;
            int r = idx >> 4, c = (idx & 15) * 8;
            cp16(&Bs[s * 9216 + r * 144 + c], &B[(size_t)(k0 + r) * N + col0 + c]);
        }
    };

    load_tile(0, 0);
    cp_commit();

    for (int t = 0; t < ntiles; t++) {
        if (t + 1 < ntiles) load_tile((t + 1) & 1, (t + 1) * 64);
        cp_commit();
        cp_wait1();
        __syncthreads();
        const int s = t & 1;

#pragma unroll
        for (int kk = 0; kk < 64; kk += 16) {
            uint32_t a[4][4], b[4][2];
#pragma unroll
            for (int mi = 0; mi < 4; mi++)
                ldmA4(a[mi], &As[s * 9216 + (wm * 64 + mi * 16 + (lane & 15)) * 72 + kk + (lane >> 4) * 8]);
#pragma unroll
            for (int ni = 0; ni < 4; ni++)
                ldmB2t(b[ni], &Bs[s * 9216 + (kk + (lane & 15)) * 144 + wn * 32 + ni * 8]);
#pragma unroll
            for (int mi = 0; mi < 4; mi++)
#pragma unroll
                for (int ni = 0; ni < 4; ni++)
                    mma16816(acc[mi][ni], a[mi], b[ni]);
        }
        __syncthreads();
    }

    // ---- epilogue ----
    const int gid = lane >> 2, tig = lane & 3;
#pragma unroll
    for (int mi = 0; mi < 4; mi++) {
#pragma unroll
        for (int ni = 0; ni < 4; ni++) {
            int gr = row0 + wm * 64 + mi * 16 + gid;
            int gc = col0 + wn * 32 + ni * 8 + tig * 2;
#pragma unroll
            for (int half = 0; half < 2; half++) {
                int r = gr + half * 8;
#pragma unroll
                for (int cc = 0; cc < 2; cc++) {
                    float c = acc[mi][ni][half * 2 + cc];
                    int col = gc + cc;
                    if (bias) c += bias[col];
                    if (GELU) c = 0.5f * c * (1.f + erff(c * 0.70710678118654752f));
                    if (SPLIT) {
                        bf16 hi, lo; split2(c, hi, lo);
                        bf16* C = (bf16*)Cv;
                        size_t base = (size_t)r * (3 * N) + col;
                        C[base] = hi; C[base + N] = hi; C[base + 2 * N] = lo;
                    } else {
                        float* C = (float*)Cv;
                        if (res) c += res[(size_t)r * N + col];
                        C[(size_t)r * N + col] = c;
                    }
                }
            }
        }
    }
}

// ---------------- tensor-core flash attention ----------------
// qkv2: split bf16 [M][3*2304]; seg0 = hi (q|k|v), seg2 (+4608) = lo.
// att2: A-side split bf16 [M][3*768].
// Block: 128 queries x (head, batch). 256 threads = 8 warps x 16 rows.
// Dynamic smem layout (bytes):
//   Qs [128][200] @ 0       (cols 0..95 Qhi, 96..191 Qlo)        51200
//   Ks [192][72]  @ 51200   (rows 0..95 Khi, 96..191 Klo; [k][key]) 27648
//   Vs [128][104] @ 78848   (rows 0..63 Vhi, 64..127 Vlo; [key][d]) 26624
//   Ps [128][136] @ 105472  (cols 0..63 Phi, 64..127 Plo)         34816
// total 140288
__global__ void __launch_bounds__(256)
attn_mma_kernel(const bf16* __restrict__ qkv2, bf16* __restrict__ att2)
{
    extern __shared__ char dynsm[];
    bf16* Qs = (bf16*)dynsm;
    bf16* Ks = (bf16*)(dynsm + 51200);
    bf16* Vs = (bf16*)(dynsm + 78848);
    bf16* Ps = (bf16*)(dynsm + 105472);

    const int qb0  = blockIdx.x * 128;
    const int h    = blockIdx.y;
    const int b    = blockIdx.z;
    const int tid  = threadIdx.x;
    const int lane = tid & 31;
    const int w    = tid >> 5;
    const int gid  = lane >> 2, tig = lane & 3;

    const size_t NQ = 3 * E3;                       // 6912
    const size_t rowbase = (size_t)(b * TT) * NQ;
    const int qoff = h * HS, koff = EE + h * HS, voff = 2 * EE + h * HS;
    const int loseg = 2 * E3;                       // 4608

    // load Q tile (hi + lo)
    for (int i = tid; i < 128 * 12; i += 256) {
        int r = i / 12, e0 = (i % 12) * 8;
        const size_t g = rowbase + (size_t)(qb0 + r) * NQ;
        *(uint4*)&Qs[r * 200 + e0]      = *(const uint4*)&qkv2[g + qoff + e0];
        *(uint4*)&Qs[r * 200 + 96 + e0] = *(const uint4*)&qkv2[g + loseg + qoff + e0];
    }

    float o[12][4];
#pragma unroll
    for (int i = 0; i < 12; i++)
#pragma unroll
        for (int j = 0; j < 4; j++) o[i][j] = 0.f;
    float mrow0 = -1e30f, mrow1 = -1e30f, lrow0 = 0.f, lrow1 = 0.f;

    const float scale = 0.10206207261596577f;   // 96^-0.5
    const int nchunks = qb0 / 64 + 2;

    for (int ch = 0; ch < nchunks; ch++) {
        const int c0 = ch * 64;
        __syncthreads();
        // load K (transposed, split) and V (split) chunk
        for (int i = tid; i < 64 * 12; i += 256) {
            int key = i / 12, e0 = (i % 12) * 8;
            const size_t g = rowbase + (size_t)(c0 + key) * NQ;
            uint4 khiv = *(const uint4*)&qkv2[g + koff + e0];
            uint4 klov = *(const uint4*)&qkv2[g + loseg + koff + e0];
            const bf16* kh = (const bf16*)&khiv;
            const bf16* kl = (const bf16*)&klov;
#pragma unroll
            for (int j = 0; j < 8; j++) {
                Ks[(e0 + j) * 72 + key]      = kh[j];
                Ks[(96 + e0 + j) * 72 + key] = kl[j];
            }
            *(uint4*)&Vs[key * 104 + e0]        = *(const uint4*)&qkv2[g + voff + e0];
            *(uint4*)&Vs[(64 + key) * 104 + e0] = *(const uint4*)&qkv2[g + loseg + voff + e0];
        }
        __syncthreads();

        // ---- S = Q K^T (3-term split) ----
        float sacc[8][4];
#pragma unroll
        for (int i = 0; i < 8; i++)
#pragma unroll
            for (int j = 0; j < 4; j++) sacc[i][j] = 0.f;

#pragma unroll
        for (int sgi = 0; sgi < 3; sgi++) {
            const int qs0 = (sgi == 2) ? 96 : 0;
            const int ks0 = (sgi == 1) ? 96 : 0;
#pragma unroll
            for (int kk = 0; kk < 96; kk += 16) {
                uint32_t a[4];
                ldmA4(a, &Qs[(w * 16 + (lane & 15)) * 200 + qs0 + kk + (lane >> 4) * 8]);
#pragma unroll
                for (int nt = 0; nt < 8; nt += 2) {
                    uint32_t bb[4];
                    ldmB4t(bb, &Ks[(ks0 + kk + (lane & 15)) * 72 + nt * 8 + (lane >> 4) * 8]);
                    mma16816(sacc[nt],     a, bb);
                    mma16816(sacc[nt + 1], a, bb + 2);
                }
            }
        }

        // ---- scale + causal mask + online softmax ----
        const int rg0 = qb0 + w * 16 + gid;
        const bool need_mask = (c0 + 64 > qb0);
        float cm0 = -1e30f, cm1 = -1e30f;
#pragma unroll
        for (int nt = 0; nt < 8; nt++) {
#pragma unroll
            for (int e = 0; e < 4; e++) {
                float s = sacc[nt][e] * scale;
                if (need_mask) {
                    int col = c0 + nt * 8 + tig * 2 + (e & 1);
                    int row = rg0 + (e >> 1) * 8;
                    if (col > row) s = -1e30f;
                }
                sacc[nt][e] = s;
                if (e < 2) cm0 = fmaxf(cm0, s); else cm1 = fmaxf(cm1, s);
            }
        }
        cm0 = fmaxf(cm0, __shfl_xor_sync(0xffffffffu, cm0, 1));
        cm0 = fmaxf(cm0, __shfl_xor_sync(0xffffffffu, cm0, 2));
        cm1 = fmaxf(cm1, __shfl_xor_sync(0xffffffffu, cm1, 1));
        cm1 = fmaxf(cm1, __shfl_xor_sync(0xffffffffu, cm1, 2));

        const float mn0 = fmaxf(mrow0, cm0), mn1 = fmaxf(mrow1, cm1);
        const float al0 = __expf(mrow0 - mn0), al1 = __expf(mrow1 - mn1);
        float cs0 = 0.f, cs1 = 0.f;
#pragma unroll
        for (int nt = 0; nt < 8; nt++) {
            float p0 = __expf(sacc[nt][0] - mn0), p1 = __expf(sacc[nt][1] - mn0);
            float p2 = __expf(sacc[nt][2] - mn1), p3 = __expf(sacc[nt][3] - mn1);
            cs0 += p0 + p1; cs1 += p2 + p3;
            bf16 h0, l0, h1, l1, h2, l2, h3, l3;
            split2(p0, h0, l0); split2(p1, h1, l1);
            split2(p2, h2, l2); split2(p3, h3, l3);
            int colb = nt * 8 + tig * 2;
            *(uint32_t*)&Ps[(w * 16 + gid) * 136 + colb]          = pack2(h0, h1);
            *(uint32_t*)&Ps[(w * 16 + gid) * 136 + 64 + colb]     = pack2(l0, l1);
            *(uint32_t*)&Ps[(w * 16 + gid + 8) * 136 + colb]      = pack2(h2, h3);
            *(uint32_t*)&Ps[(w * 16 + gid + 8) * 136 + 64 + colb] = pack2(l2, l3);
        }
        cs0 += __shfl_xor_sync(0xffffffffu, cs0, 1);
        cs0 += __shfl_xor_sync(0xffffffffu, cs0, 2);
        cs1 += __shfl_xor_sync(0xffffffffu, cs1, 1);
        cs1 += __shfl_xor_sync(0xffffffffu, cs1, 2);

        lrow0 = lrow0 * al0 + cs0; lrow1 = lrow1 * al1 + cs1;
        mrow0 = mn0; mrow1 = mn1;
#pragma unroll
        for (int nt = 0; nt < 12; nt++) {
            o[nt][0] *= al0; o[nt][1] *= al0; o[nt][2] *= al1; o[nt][3] *= al1;
        }
        __syncwarp();

        // ---- O += P V (3-term split) ----
#pragma unroll
        for (int sgi = 0; sgi < 3; sgi++) {
            const int as0 = (sgi == 2) ? 64 : 0;
            const int bs0 = (sgi == 1) ? 64 : 0;
#pragma unroll
            for (int kk = 0; kk < 64; kk += 16) {
                uint32_t a[4];
                ldmA4(a, &Ps[(w * 16 + (lane & 15)) * 136 + as0 + kk + (lane >> 4) * 8]);
#pragma unroll
                for (int nt = 0; nt < 12; nt += 2) {
                    uint32_t bb[4];
                    ldmB4t(bb, &Vs[(bs0 + kk + (lane & 15)) * 104 + nt * 8 + (lane >> 4) * 8]);
                    mma16816(o[nt],     a, bb);
                    mma16816(o[nt + 1], a, bb + 2);
                }
            }
        }
    }

    // ---- epilogue: O /= l, write att2 A-side split [hi | hi | lo] ----
    const float iv0 = 1.f / lrow0, iv1 = 1.f / lrow1;
#pragma unroll
    for (int nt = 0; nt < 12; nt++) {
        int d = h * HS + nt * 8 + tig * 2;
        {
            size_t orow = (size_t)(b * TT + qb0 + w * 16 + gid) * E3;
            float v0 = o[nt][0] * iv0, v1 = o[nt][1] * iv0;
            bf16 h0, l0, h1, l1; split2(v0, h0, l0); split2(v1, h1, l1);
            *(uint32_t*)&att2[orow + d]          = pack2(h0, h1);
            *(uint32_t*)&att2[orow + EE + d]     = pack2(h0, h1);
            *(uint32_t*)&att2[orow + 2 * EE + d] = pack2(l0, l1);
        }
        {
            size_t orow = (size_t)(b * TT + qb0 + w * 16 + gid + 8) * E3;
            float v0 = o[nt][2] * iv1, v1 = o[nt][3] * iv1;
            bf16 h0, l0, h1, l1; split2(v0, h0, l0); split2(v1, h1, l1);
            *(uint32_t*)&att2[orow + d]          = pack2(h0, h1);
            *(uint32_t*)&att2[orow + EE + d]     = pack2(h0, h1);
            *(uint32_t*)&att2[orow + 2 * EE + d] = pack2(l0, l1);
        }
    }
}

// ---------------- loss ----------------
__global__ void loss_zero_kernel(float* loss) { *loss = 0.f; }

__global__ void loss_kernel(const float* __restrict__ logits,
                            const int* __restrict__ targets,
                            float* __restrict__ loss)
{
    const int row = blockIdx.x;
    const int tid = threadIdx.x;   // 256
    const float* lr = logits + (size_t)row * VV;

    __shared__ float red[256];
    float lmax = -1e30f;
    for (int j = tid; j < VV; j += 256) lmax = fmaxf(lmax, lr[j]);
    red[tid] = lmax; __syncthreads();
    for (int o = 128; o > 0; o >>= 1) {
        if (tid < o) red[tid] = fmaxf(red[tid], red[tid + o]);
        __syncthreads();
    }
    const float m = red[0];
    __syncthreads();

    float lsum = 0.f;
    for (int j = tid; j < VV; j += 256) lsum += expf(lr[j] - m);
    red[tid] = lsum; __syncthreads();
    for (int o = 128; o > 0; o >>= 1) {
        if (tid < o) red[tid] += red[tid + o];
        __syncthreads();
    }
    if (tid == 0) {
        float lp = lr[targets[row]] - m - logf(red[0]);
        atomicAdd(loss, -lp * (1.f / (float)MM));
    }
}

// ---------------- launch ----------------
extern "C" void kernel_launch(void* const* d_in, const int* in_sizes, int n_in,
                              void* d_out, int out_size)
{
    const int*   idx     = (const int*)  d_in[0];
    const int*   targets = (const int*)  d_in[1];
    const float* tok     = (const float*)d_in[2];
    const float* pos     = (const float*)d_in[3];
    const float* Wq      = (const float*)d_in[4];
    const float* Wk      = (const float*)d_in[5];
    const float* Wv      = (const float*)d_in[6];
    const float* Wo      = (const float*)d_in[7];
    const float* bo      = (const float*)d_in[8];
    const float* ln1_g   = (const float*)d_in[9];
    const float* ln1_b   = (const float*)d_in[10];
    const float* ln2_g   = (const float*)d_in[11];
    const float* ln2_b   = (const float*)d_in[12];
    const float* W1      = (const float*)d_in[13];
    const float* b1      = (const float*)d_in[14];
    const float* W2      = (const float*)d_in[15];
    const float* b2      = (const float*)d_in[16];
    const float* lnf_g   = (const float*)d_in[17];
    const float* lnf_b   = (const float*)d_in[18];

    float *x, *lg_scratch;
    bf16 *xn2, *qkv2, *att2, *h42, *wqkv2, *wo2, *w12, *w22, *tok2;
    cudaGetSymbolAddress((void**)&x,    g_x);
    cudaGetSymbolAddress((void**)&xn2,  g_xn2);
    cudaGetSymbolAddress((void**)&qkv2, g_qkv2);
    cudaGetSymbolAddress((void**)&att2, g_att2);
    cudaGetSymbolAddress((void**)&h42,  g_h42);
    cudaGetSymbolAddress((void**)&wqkv2,g_wqkv2);
    cudaGetSymbolAddress((void**)&wo2,  g_wo2);
    cudaGetSymbolAddress((void**)&w12,  g_w12);
    cudaGetSymbolAddress((void**)&w22,  g_w22);
    cudaGetSymbolAddress((void**)&tok2, g_tok2);
    cudaGetSymbolAddress((void**)&lg_scratch, g_logits_scratch);

    const int GEMM_SMEM = 73728;
    const int ATTN_SMEM = 140288;
    cudaFuncSetAttribute(mma_gemm<false,false>, cudaFuncAttributeMaxDynamicSharedMemorySize, GEMM_SMEM);
    cudaFuncSetAttribute(mma_gemm<false,true >, cudaFuncAttributeMaxDynamicSharedMemorySize, GEMM_SMEM);
    cudaFuncSetAttribute(mma_gemm<true ,true >, cudaFuncAttributeMaxDynamicSharedMemorySize, GEMM_SMEM);
    cudaFuncSetAttribute(attn_mma_kernel, cudaFuncAttributeMaxDynamicSharedMemorySize, ATTN_SMEM);

    const bool out_holds_logits = ((long long)out_size >= (long long)MM * VV);
    float* logits = out_holds_logits ? (float*)d_out : lg_scratch;

    // ---- weight conversions ----
    {
        const int gEE = (EE * EE + 255) / 256;
        const int gEF = (EE * FF + 255) / 256;
        const int gFE = (FF * EE + 255) / 256;
        for (int l = 0; l < LL; l++) {
            const size_t oEE = (size_t)l * EE * EE;
            bf16* wq2l = wqkv2 + (size_t)l * E3 * E3;
            convert_w_kernel<<<gEE, 256>>>(Wq + oEE, wq2l, EE, EE, E3, 0);
            convert_w_kernel<<<gEE, 256>>>(Wk + oEE, wq2l, EE, EE, E3, EE);
            convert_w_kernel<<<gEE, 256>>>(Wv + oEE, wq2l, EE, EE, E3, 2 * EE);
            convert_w_kernel<<<gEE, 256>>>(Wo + oEE, wo2 + (size_t)l * E3 * EE, EE, EE, EE, 0);
            convert_w_kernel<<<gEF, 256>>>(W1 + (size_t)l * EE * FF, w12 + (size_t)l * E3 * FF, EE, FF, FF, 0);
            convert_w_kernel<<<gFE, 256>>>(W2 + (size_t)l * FF * EE, w22 + (size_t)l * F3 * EE, FF, EE, EE, 0);
        }
        convert_tok_kernel<<<dim3(EE / 32, VV / 32), dim3(32, 32)>>>(tok, tok2);
    }

    // ---- embedding ----
    {
        size_t n = (size_t)MM * EE;
        embed_kernel<<<(unsigned)((n + 255) / 256), 256>>>(idx, tok, pos, x);
    }

    const dim3 gQKV(E3 / 128, MM / 128);
    const dim3 gE  (EE / 128, MM / 128);
    const dim3 gF  (FF / 128, MM / 128);
    const dim3 gV  (VV / 128, MM / 128);

    for (int l = 0; l < LL; l++) {
        ln_split_kernel<<<MM, 256>>>(x, ln1_g + (size_t)l * EE, ln1_b + (size_t)l * EE, xn2);
        // qkv (split output for attention)
        mma_gemm<false, true><<<gQKV, 256, GEMM_SMEM>>>(xn2, wqkv2 + (size_t)l * E3 * E3,
                                                        nullptr, nullptr, qkv2, MM, E3, E3);
        attn_mma_kernel<<<dim3(TT / 128, HH, BB), 256, ATTN_SMEM>>>(qkv2, att2);
        // x = x + att @ Wo + bo
        mma_gemm<false, false><<<gE, 256, GEMM_SMEM>>>(att2, wo2 + (size_t)l * E3 * EE,
                                                       bo + (size_t)l * EE, x, x, MM, EE, E3);
        ln_split_kernel<<<MM, 256>>>(x, ln2_g + (size_t)l * EE, ln2_b + (size_t)l * EE, xn2);
        mma_gemm<true, true><<<gF, 256, GEMM_SMEM>>>(xn2, w12 + (size_t)l * E3 * FF,
                                                     b1 + (size_t)l * FF, nullptr, h42, MM, FF, E3);
        mma_gemm<false, false><<<gE, 256, GEMM_SMEM>>>(h42, w22 + (size_t)l * F3 * EE,
                                                       b2 + (size_t)l * EE, x, x, MM, EE, F3);
    }

    ln_split_kernel<<<MM, 256>>>(x, lnf_g, lnf_b, xn2);
    mma_gemm<false, false><<<gV, 256, GEMM_SMEM>>>(xn2, tok2, nullptr, nullptr, logits, MM, VV, E3);

    float* loss_ptr = out_holds_logits ? ((float*)d_out + (size_t)MM * VV)
                                       : (float*)d_out;
    if (!out_holds_logits || (long long)out_size > (long long)MM * VV) {
        loss_zero_kernel<<<1, 1>>>(loss_ptr);
        loss_kernel<<<MM, 256>>>(logits, targets, loss_ptr);
    }
}

// round 6
// speedup vs baseline: 6.5252x; 1.0290x over previous
#include <cuda_runtime.h>
#include <cuda_bf16.h>
#include <math.h>
#include <stdint.h>

// ---------------- problem constants ----------------
#define BB 4
#define TT 1024
#define EE 768
#define HH 8
#define HS 96
#define LL 8
#define VV 32000
#define FF 3072            // 4*E
#define MM (BB*TT)         // 4096 rows
#define E3 (3*EE)          // 2304 (split-K for E)
#define F3 (3*FF)          // 9216 (split-K for 4E)

typedef __nv_bfloat16 bf16;

// ---------------- scratch (device globals; no allocation allowed) ----------------
__device__ __align__(256) float g_x   [(size_t)MM*EE];
__device__ __align__(256) bf16  g_xn2 [(size_t)MM*E3];
__device__ __align__(256) bf16  g_qkv2[(size_t)MM*3*E3];       // QKV GEMM split output [M][3*2304]
__device__ __align__(256) bf16  g_att2[(size_t)MM*E3];
__device__ __align__(256) bf16  g_h42 [(size_t)MM*F3];

__device__ __align__(256) bf16  g_wqkv2[(size_t)LL*E3*E3];     // [l][3K=2304][N=2304]
__device__ __align__(256) bf16  g_wo2  [(size_t)LL*E3*EE];
__device__ __align__(256) bf16  g_w12  [(size_t)LL*E3*FF];
__device__ __align__(256) bf16  g_w22  [(size_t)LL*F3*EE];
__device__ __align__(256) bf16  g_tok2 [(size_t)E3*VV];

__device__ __align__(256) float g_logits_scratch[(size_t)MM*VV];

// ---------------- helpers ----------------
__device__ __forceinline__ void split2(float v, bf16& hi, bf16& lo) {
    hi = __float2bfloat16(v);
    lo = __float2bfloat16(v - __bfloat162float(hi));
}
__device__ __forceinline__ uint32_t pack2(bf16 a, bf16 b) {
    uint16_t x = *(uint16_t*)&a, y = *(uint16_t*)&b;
    return (uint32_t)x | ((uint32_t)y << 16);
}

__device__ __forceinline__ void cp16(void* dst_smem, const void* src_gmem) {
    uint32_t s = (uint32_t)__cvta_generic_to_shared(dst_smem);
    asm volatile("cp.async.cg.shared.global [%0], [%1], 16;\n" :: "r"(s), "l"(src_gmem));
}
__device__ __forceinline__ void cp_commit() { asm volatile("cp.async.commit_group;\n" ::: "memory"); }
__device__ __forceinline__ void cp_wait1()  { asm volatile("cp.async.wait_group 1;\n" ::: "memory"); }

__device__ __forceinline__ void ldmA4(uint32_t* a, const void* p) {
    uint32_t s = (uint32_t)__cvta_generic_to_shared(p);
    asm volatile("ldmatrix.sync.aligned.m8n8.x4.shared.b16 {%0,%1,%2,%3}, [%4];"
                 : "=r"(a[0]), "=r"(a[1]), "=r"(a[2]), "=r"(a[3]) : "r"(s));
}
__device__ __forceinline__ void ldmB4t(uint32_t* b, const void* p) {
    uint32_t s = (uint32_t)__cvta_generic_to_shared(p);
    asm volatile("ldmatrix.sync.aligned.m8n8.x4.trans.shared.b16 {%0,%1,%2,%3}, [%4];"
                 : "=r"(b[0]), "=r"(b[1]), "=r"(b[2]), "=r"(b[3]) : "r"(s));
}
__device__ __forceinline__ void mma16816(float* c, const uint32_t* a, const uint32_t* b) {
    asm volatile(
        "mma.sync.aligned.m16n8k16.row.col.f32.bf16.bf16.f32 "
        "{%0,%1,%2,%3},{%4,%5,%6,%7},{%8,%9},{%0,%1,%2,%3};"
        : "+f"(c[0]), "+f"(c[1]), "+f"(c[2]), "+f"(c[3])
        : "r"(a[0]), "r"(a[1]), "r"(a[2]), "r"(a[3]), "r"(b[0]), "r"(b[1]));
}

// ---------------- embedding ----------------
__global__ void embed_kernel(const int* __restrict__ idx,
                             const float* __restrict__ tok,
                             const float* __restrict__ pos,
                             float* __restrict__ x)
{
    size_t i = (size_t)blockIdx.x * blockDim.x + threadIdx.x;
    if (i >= (size_t)MM * EE) return;
    int e  = (int)(i % EE);
    int bt = (int)(i / EE);
    int t  = bt % TT;
    x[i] = tok[(size_t)idx[bt] * EE + e] + pos[(size_t)t * EE + e];
}

// ---------------- layernorm -> A-side split bf16 [row, 3E]: [hi | hi | lo] ----------------
__global__ void ln_split_kernel(const float* __restrict__ x,
                                const float* __restrict__ g,
                                const float* __restrict__ b,
                                bf16* __restrict__ out)
{
    int row = blockIdx.x;
    int tid = threadIdx.x;  // 256
    const float* xr = x + (size_t)row * EE;
    float s = 0.f, s2 = 0.f;
    for (int e = tid; e < EE; e += 256) { float v = xr[e]; s += v; s2 += v * v; }
    __shared__ float r1[256], r2[256];
    r1[tid] = s; r2[tid] = s2; __syncthreads();
    for (int o = 128; o > 0; o >>= 1) {
        if (tid < o) { r1[tid] += r1[tid + o]; r2[tid] += r2[tid + o]; }
        __syncthreads();
    }
    float mean = r1[0] * (1.f / EE);
    float var  = r2[0] * (1.f / EE) - mean * mean;
    float inv  = rsqrtf(var + 1e-5f);
    bf16* orow = out + (size_t)row * E3;
    for (int e = tid; e < EE; e += 256) {
        float v = (xr[e] - mean) * inv * g[e] + b[e];
        bf16 hi, lo; split2(v, hi, lo);
        orow[e] = hi; orow[EE + e] = hi; orow[2*EE + e] = lo;
    }
}

// ---------------- weight conversion (all layers in one launch; blockIdx.y = layer) ----------
// W[K,N] fp32 -> B-side rows [hi; lo; hi]
__global__ void convert_w_kernel(const float* __restrict__ W, bf16* __restrict__ out,
                                 int K, int N, int pitch, int colOff,
                                 size_t wstride, size_t ostride)
{
    const int l = blockIdx.y;
    const float* Wl = W + (size_t)l * wstride;
    bf16* outl = out + (size_t)l * ostride;
    int i = blockIdx.x * 256 + threadIdx.x;
    if (i >= K * N) return;
    int k = i / N, n = i % N;
    float v = Wl[i];
    bf16 hi, lo; split2(v, hi, lo);
    outl[(size_t)k * pitch + colOff + n]           = hi;
    outl[(size_t)(K + k) * pitch + colOff + n]     = lo;
    outl[(size_t)(2 * K + k) * pitch + colOff + n] = hi;
}

// Contract: A segments [hi | hi | lo], B rows [hi; lo; hi]
//   seg0: Ahi*Bhi, seg1: Ahi*Blo, seg2: Alo*Bhi   (lo*lo dropped, ~2^-18)

// ---------------- tok transpose + split: out[3E, V] from tok[V, E] (B-side) ----------------
__global__ void convert_tok_kernel(const float* __restrict__ tok, bf16* __restrict__ out)
{
    __shared__ float t[32][33];
    int k0 = blockIdx.x * 32, n0 = blockIdx.y * 32;
    int tx = threadIdx.x, ty = threadIdx.y;
    t[ty][tx] = tok[(size_t)(n0 + ty) * EE + k0 + tx];
    __syncthreads();
    float v = t[tx][ty];
    bf16 hi, lo; split2(v, hi, lo);
    size_t k = k0 + ty, n = n0 + tx;
    out[k * VV + n]              = hi;
    out[(EE + k) * VV + n]       = lo;
    out[(2*EE + k) * VV + n]     = hi;
}

// ---------------- tensor-core GEMM: C[M,N] = A[M,K2] @ B[K2,N] ----------------
// Persistent CTAs over tiles (col-major order for B reuse in L2).
// K-tile 64, 2-stage cp.async, 2 CTAs/SM. Dynamic smem = 73728 B.
template<bool GELU, bool SPLIT>
__global__ void __launch_bounds__(256, 2)
mma_gemm(const bf16* __restrict__ A, const bf16* __restrict__ B,
         const float* __restrict__ bias, const float* __restrict__ res,
         void* __restrict__ Cv, int M, int N, int K2)
{
    extern __shared__ char dynsm[];
    bf16* As = (bf16*)dynsm;            // [2][128*72]
    bf16* Bs = (bf16*)dynsm + 18432;    // [2][64*144]

    const int tid  = threadIdx.x;
    const int lane = tid & 31;
    const int warp = tid >> 5;
    const int wm   = warp & 1;
    const int wn   = warp >> 1;

    const int nRowT = M >> 7;
    const int nColT = N >> 7;
    const int nTiles = nRowT * nColT;
    const int ntk = K2 >> 6;

    for (int tile = blockIdx.x; tile < nTiles; tile += gridDim.x) {
        // col-major: consecutive tiles share the column (B tile stays hot in L2)
        const int col0 = (tile / nRowT) * 128;
        const int row0 = (tile % nRowT) * 128;

        float acc[4][4][4];
#pragma unroll
        for (int i = 0; i < 4; i++)
#pragma unroll
            for (int j = 0; j < 4; j++)
#pragma unroll
                for (int r = 0; r < 4; r++) acc[i][j][r] = 0.f;

        auto load_tile = [&](int s, int k0) {
#pragma unroll
            for (int i = 0; i < 4; i++) {
                int idx = tid + i * 256;
                int r = idx >> 3, c = (idx & 7) * 8;
                cp16(&As[s * 9216 + r * 72 + c], &A[(size_t)(row0 + r) * K2 + k0 + c]);
            }
#pragma unroll
            for (int i = 0; i < 4; i++) {
                int idx = tid + i * 256;
                int r = idx >> 4, c = (idx & 15) * 8;
                cp16(&Bs[s * 9216 + r * 144 + c], &B[(size_t)(k0 + r) * N + col0 + c]);
            }
        };

        __syncthreads();   // protect smem from previous tile's consumers
        load_tile(0, 0);
        cp_commit();

        for (int t = 0; t < ntk; t++) {
            if (t + 1 < ntk) load_tile((t + 1) & 1, (t + 1) * 64);
            cp_commit();
            cp_wait1();
            __syncthreads();
            const int s = t & 1;

#pragma unroll
            for (int kk = 0; kk < 64; kk += 16) {
                uint32_t a[4][4], b[2][4];
#pragma unroll
                for (int mi = 0; mi < 4; mi++)
                    ldmA4(a[mi], &As[s * 9216 + (wm * 64 + mi * 16 + (lane & 15)) * 72 + kk + (lane >> 4) * 8]);
#pragma unroll
                for (int nj = 0; nj < 2; nj++)
                    ldmB4t(b[nj], &Bs[s * 9216 + (kk + (lane & 15)) * 144 + wn * 32 + nj * 16 + (lane >> 4) * 8]);
#pragma unroll
                for (int mi = 0; mi < 4; mi++) {
                    mma16816(acc[mi][0], a[mi], b[0]);
                    mma16816(acc[mi][1], a[mi], b[0] + 2);
                    mma16816(acc[mi][2], a[mi], b[1]);
                    mma16816(acc[mi][3], a[mi], b[1] + 2);
                }
            }
            __syncthreads();
        }

        // ---- epilogue ----
        const int gid = lane >> 2, tig = lane & 3;
#pragma unroll
        for (int mi = 0; mi < 4; mi++) {
#pragma unroll
            for (int ni = 0; ni < 4; ni++) {
                int gr = row0 + wm * 64 + mi * 16 + gid;
                int gc = col0 + wn * 32 + ni * 8 + tig * 2;
#pragma unroll
                for (int half = 0; half < 2; half++) {
                    int r = gr + half * 8;
#pragma unroll
                    for (int cc = 0; cc < 2; cc++) {
                        float c = acc[mi][ni][half * 2 + cc];
                        int col = gc + cc;
                        if (bias) c += bias[col];
                        if (GELU) c = 0.5f * c * (1.f + erff(c * 0.70710678118654752f));
                        if (SPLIT) {
                            bf16 hi, lo; split2(c, hi, lo);
                            bf16* C = (bf16*)Cv;
                            size_t base = (size_t)r * (3 * N) + col;
                            C[base] = hi; C[base + N] = hi; C[base + 2 * N] = lo;
                        } else {
                            float* C = (float*)Cv;
                            if (res) c += res[(size_t)r * N + col];
                            C[(size_t)r * N + col] = c;
                        }
                    }
                }
            }
        }
    }
}

// ---------------- tensor-core flash attention (unchanged from R5) ----------------
__global__ void __launch_bounds__(256)
attn_mma_kernel(const bf16* __restrict__ qkv2, bf16* __restrict__ att2)
{
    extern __shared__ char dynsm[];
    bf16* Qs = (bf16*)dynsm;
    bf16* Ks = (bf16*)(dynsm + 51200);
    bf16* Vs = (bf16*)(dynsm + 78848);
    bf16* Ps = (bf16*)(dynsm + 105472);

    const int qb0  = blockIdx.x * 128;
    const int h    = blockIdx.y;
    const int b    = blockIdx.z;
    const int tid  = threadIdx.x;
    const int lane = tid & 31;
    const int w    = tid >> 5;
    const int gid  = lane >> 2, tig = lane & 3;

    const size_t NQ = 3 * E3;
    const size_t rowbase = (size_t)(b * TT) * NQ;
    const int qoff = h * HS, koff = EE + h * HS, voff = 2 * EE + h * HS;
    const int loseg = 2 * E3;

    for (int i = tid; i < 128 * 12; i += 256) {
        int r = i / 12, e0 = (i % 12) * 8;
        const size_t g = rowbase + (size_t)(qb0 + r) * NQ;
        *(uint4*)&Qs[r * 200 + e0]      = *(const uint4*)&qkv2[g + qoff + e0];
        *(uint4*)&Qs[r * 200 + 96 + e0] = *(const uint4*)&qkv2[g + loseg + qoff + e0];
    }

    float o[12][4];
#pragma unroll
    for (int i = 0; i < 12; i++)
#pragma unroll
        for (int j = 0; j < 4; j++) o[i][j] = 0.f;
    float mrow0 = -1e30f, mrow1 = -1e30f, lrow0 = 0.f, lrow1 = 0.f;

    const float scale = 0.10206207261596577f;
    const int nchunks = qb0 / 64 + 2;

    for (int ch = 0; ch < nchunks; ch++) {
        const int c0 = ch * 64;
        __syncthreads();
        for (int i = tid; i < 64 * 12; i += 256) {
            int key = i / 12, e0 = (i % 12) * 8;
            const size_t g = rowbase + (size_t)(c0 + key) * NQ;
            uint4 khiv = *(const uint4*)&qkv2[g + koff + e0];
            uint4 klov = *(const uint4*)&qkv2[g + loseg + koff + e0];
            const bf16* kh = (const bf16*)&khiv;
            const bf16* kl = (const bf16*)&klov;
#pragma unroll
            for (int j = 0; j < 8; j++) {
                Ks[(e0 + j) * 72 + key]      = kh[j];
                Ks[(96 + e0 + j) * 72 + key] = kl[j];
            }
            *(uint4*)&Vs[key * 104 + e0]        = *(const uint4*)&qkv2[g + voff + e0];
            *(uint4*)&Vs[(64 + key) * 104 + e0] = *(const uint4*)&qkv2[g + loseg + voff + e0];
        }
        __syncthreads();

        float sacc[8][4];
#pragma unroll
        for (int i = 0; i < 8; i++)
#pragma unroll
            for (int j = 0; j < 4; j++) sacc[i][j] = 0.f;

#pragma unroll
        for (int sgi = 0; sgi < 3; sgi++) {
            const int qs0 = (sgi == 2) ? 96 : 0;
            const int ks0 = (sgi == 1) ? 96 : 0;
#pragma unroll
            for (int kk = 0; kk < 96; kk += 16) {
                uint32_t a[4];
                ldmA4(a, &Qs[(w * 16 + (lane & 15)) * 200 + qs0 + kk + (lane >> 4) * 8]);
#pragma unroll
                for (int nt = 0; nt < 8; nt += 2) {
                    uint32_t bb[4];
                    ldmB4t(bb, &Ks[(ks0 + kk + (lane & 15)) * 72 + nt * 8 + (lane >> 4) * 8]);
                    mma16816(sacc[nt],     a, bb);
                    mma16816(sacc[nt + 1], a, bb + 2);
                }
            }
        }

        const int rg0 = qb0 + w * 16 + gid;
        const bool need_mask = (c0 + 64 > qb0);
        float cm0 = -1e30f, cm1 = -1e30f;
#pragma unroll
        for (int nt = 0; nt < 8; nt++) {
#pragma unroll
            for (int e = 0; e < 4; e++) {
                float s = sacc[nt][e] * scale;
                if (need_mask) {
                    int col = c0 + nt * 8 + tig * 2 + (e & 1);
                    int row = rg0 + (e >> 1) * 8;
                    if (col > row) s = -1e30f;
                }
                sacc[nt][e] = s;
                if (e < 2) cm0 = fmaxf(cm0, s); else cm1 = fmaxf(cm1, s);
            }
        }
        cm0 = fmaxf(cm0, __shfl_xor_sync(0xffffffffu, cm0, 1));
        cm0 = fmaxf(cm0, __shfl_xor_sync(0xffffffffu, cm0, 2));
        cm1 = fmaxf(cm1, __shfl_xor_sync(0xffffffffu, cm1, 1));
        cm1 = fmaxf(cm1, __shfl_xor_sync(0xffffffffu, cm1, 2));

        const float mn0 = fmaxf(mrow0, cm0), mn1 = fmaxf(mrow1, cm1);
        const float al0 = __expf(mrow0 - mn0), al1 = __expf(mrow1 - mn1);
        float cs0 = 0.f, cs1 = 0.f;
#pragma unroll
        for (int nt = 0; nt < 8; nt++) {
            float p0 = __expf(sacc[nt][0] - mn0), p1 = __expf(sacc[nt][1] - mn0);
            float p2 = __expf(sacc[nt][2] - mn1), p3 = __expf(sacc[nt][3] - mn1);
            cs0 += p0 + p1; cs1 += p2 + p3;
            bf16 h0, l0, h1, l1, h2, l2, h3, l3;
            split2(p0, h0, l0); split2(p1, h1, l1);
            split2(p2, h2, l2); split2(p3, h3, l3);
            int colb = nt * 8 + tig * 2;
            *(uint32_t*)&Ps[(w * 16 + gid) * 136 + colb]          = pack2(h0, h1);
            *(uint32_t*)&Ps[(w * 16 + gid) * 136 + 64 + colb]     = pack2(l0, l1);
            *(uint32_t*)&Ps[(w * 16 + gid + 8) * 136 + colb]      = pack2(h2, h3);
            *(uint32_t*)&Ps[(w * 16 + gid + 8) * 136 + 64 + colb] = pack2(l2, l3);
        }
        cs0 += __shfl_xor_sync(0xffffffffu, cs0, 1);
        cs0 += __shfl_xor_sync(0xffffffffu, cs0, 2);
        cs1 += __shfl_xor_sync(0xffffffffu, cs1, 1);
        cs1 += __shfl_xor_sync(0xffffffffu, cs1, 2);

        lrow0 = lrow0 * al0 + cs0; lrow1 = lrow1 * al1 + cs1;
        mrow0 = mn0; mrow1 = mn1;
#pragma unroll
        for (int nt = 0; nt < 12; nt++) {
            o[nt][0] *= al0; o[nt][1] *= al0; o[nt][2] *= al1; o[nt][3] *= al1;
        }
        __syncwarp();

#pragma unroll
        for (int sgi = 0; sgi < 3; sgi++) {
            const int as0 = (sgi == 2) ? 64 : 0;
            const int bs0 = (sgi == 1) ? 64 : 0;
#pragma unroll
            for (int kk = 0; kk < 64; kk += 16) {
                uint32_t a[4];
                ldmA4(a, &Ps[(w * 16 + (lane & 15)) * 136 + as0 + kk + (lane >> 4) * 8]);
#pragma unroll
                for (int nt = 0; nt < 12; nt += 2) {
                    uint32_t bb[4];
                    ldmB4t(bb, &Vs[(bs0 + kk + (lane & 15)) * 104 + nt * 8 + (lane >> 4) * 8]);
                    mma16816(o[nt],     a, bb);
                    mma16816(o[nt + 1], a, bb + 2);
                }
            }
        }
    }

    const float iv0 = 1.f / lrow0, iv1 = 1.f / lrow1;
#pragma unroll
    for (int nt = 0; nt < 12; nt++) {
        int d = h * HS + nt * 8 + tig * 2;
        {
            size_t orow = (size_t)(b * TT + qb0 + w * 16 + gid) * E3;
            float v0 = o[nt][0] * iv0, v1 = o[nt][1] * iv0;
            bf16 h0, l0, h1, l1; split2(v0, h0, l0); split2(v1, h1, l1);
            *(uint32_t*)&att2[orow + d]          = pack2(h0, h1);
            *(uint32_t*)&att2[orow + EE + d]     = pack2(h0, h1);
            *(uint32_t*)&att2[orow + 2 * EE + d] = pack2(l0, l1);
        }
        {
            size_t orow = (size_t)(b * TT + qb0 + w * 16 + gid + 8) * E3;
            float v0 = o[nt][2] * iv1, v1 = o[nt][3] * iv1;
            bf16 h0, l0, h1, l1; split2(v0, h0, l0); split2(v1, h1, l1);
            *(uint32_t*)&att2[orow + d]          = pack2(h0, h1);
            *(uint32_t*)&att2[orow + EE + d]     = pack2(h0, h1);
            *(uint32_t*)&att2[orow + 2 * EE + d] = pack2(l0, l1);
        }
    }
}

// ---------------- loss (single pass, online logsumexp) ----------------
__global__ void loss_zero_kernel(float* loss) { *loss = 0.f; }

__global__ void loss_kernel(const float* __restrict__ logits,
                            const int* __restrict__ targets,
                            float* __restrict__ loss)
{
    const int row = blockIdx.x;
    const int tid = threadIdx.x;   // 256
    const float* lr = logits + (size_t)row * VV;

    float m = -1e30f, s = 0.f;
    for (int j = tid; j < VV; j += 256) {
        float v = lr[j];
        if (v > m) { s = s * __expf(m - v) + 1.f; m = v; }
        else       { s += __expf(v - m); }
    }
    __shared__ float rm[256], rs[256];
    rm[tid] = m; rs[tid] = s; __syncthreads();
    for (int o = 128; o > 0; o >>= 1) {
        if (tid < o) {
            float m2 = rm[tid + o], s2 = rs[tid + o];
            float mm = fmaxf(rm[tid], m2);
            rs[tid] = rs[tid] * __expf(rm[tid] - mm) + s2 * __expf(m2 - mm);
            rm[tid] = mm;
        }
        __syncthreads();
    }
    if (tid == 0) {
        float lp = lr[targets[row]] - rm[0] - logf(rs[0]);
        atomicAdd(loss, -lp * (1.f / (float)MM));
    }
}

// ---------------- launch ----------------
extern "C" void kernel_launch(void* const* d_in, const int* in_sizes, int n_in,
                              void* d_out, int out_size)
{
    const int*   idx     = (const int*)  d_in[0];
    const int*   targets = (const int*)  d_in[1];
    const float* tok     = (const float*)d_in[2];
    const float* pos     = (const float*)d_in[3];
    const float* Wq      = (const float*)d_in[4];
    const float* Wk      = (const float*)d_in[5];
    const float* Wv      = (const float*)d_in[6];
    const float* Wo      = (const float*)d_in[7];
    const float* bo      = (const float*)d_in[8];
    const float* ln1_g   = (const float*)d_in[9];
    const float* ln1_b   = (const float*)d_in[10];
    const float* ln2_g   = (const float*)d_in[11];
    const float* ln2_b   = (const float*)d_in[12];
    const float* W1      = (const float*)d_in[13];
    const float* b1      = (const float*)d_in[14];
    const float* W2      = (const float*)d_in[15];
    const float* b2      = (const float*)d_in[16];
    const float* lnf_g   = (const float*)d_in[17];
    const float* lnf_b   = (const float*)d_in[18];

    float *x, *lg_scratch;
    bf16 *xn2, *qkv2, *att2, *h42, *wqkv2, *wo2, *w12, *w22, *tok2;
    cudaGetSymbolAddress((void**)&x,    g_x);
    cudaGetSymbolAddress((void**)&xn2,  g_xn2);
    cudaGetSymbolAddress((void**)&qkv2, g_qkv2);
    cudaGetSymbolAddress((void**)&att2, g_att2);
    cudaGetSymbolAddress((void**)&h42,  g_h42);
    cudaGetSymbolAddress((void**)&wqkv2,g_wqkv2);
    cudaGetSymbolAddress((void**)&wo2,  g_wo2);
    cudaGetSymbolAddress((void**)&w12,  g_w12);
    cudaGetSymbolAddress((void**)&w22,  g_w22);
    cudaGetSymbolAddress((void**)&tok2, g_tok2);
    cudaGetSymbolAddress((void**)&lg_scratch, g_logits_scratch);

    const int GEMM_SMEM = 73728;
    const int ATTN_SMEM = 140288;
    cudaFuncSetAttribute(mma_gemm<false,false>, cudaFuncAttributeMaxDynamicSharedMemorySize, GEMM_SMEM);
    cudaFuncSetAttribute(mma_gemm<false,true >, cudaFuncAttributeMaxDynamicSharedMemorySize, GEMM_SMEM);
    cudaFuncSetAttribute(mma_gemm<true ,true >, cudaFuncAttributeMaxDynamicSharedMemorySize, GEMM_SMEM);
    cudaFuncSetAttribute(attn_mma_kernel, cudaFuncAttributeMaxDynamicSharedMemorySize, ATTN_SMEM);

    const bool out_holds_logits = ((long long)out_size >= (long long)MM * VV);
    float* logits = out_holds_logits ? (float*)d_out : lg_scratch;

    // ---- weight conversions (batched over layers) ----
    {
        const int gEE = (EE * EE + 255) / 256;
        const int gEF = (EE * FF + 255) / 256;
        const int gFE = (FF * EE + 255) / 256;
        convert_w_kernel<<<dim3(gEE, LL), 256>>>(Wq, wqkv2, EE, EE, E3, 0,
                                                 (size_t)EE*EE, (size_t)E3*E3);
        convert_w_kernel<<<dim3(gEE, LL), 256>>>(Wk, wqkv2, EE, EE, E3, EE,
                                                 (size_t)EE*EE, (size_t)E3*E3);
        convert_w_kernel<<<dim3(gEE, LL), 256>>>(Wv, wqkv2, EE, EE, E3, 2 * EE,
                                                 (size_t)EE*EE, (size_t)E3*E3);
        convert_w_kernel<<<dim3(gEE, LL), 256>>>(Wo, wo2, EE, EE, EE, 0,
                                                 (size_t)EE*EE, (size_t)E3*EE);
        convert_w_kernel<<<dim3(gEF, LL), 256>>>(W1, w12, EE, FF, FF, 0,
                                                 (size_t)EE*FF, (size_t)E3*FF);
        convert_w_kernel<<<dim3(gFE, LL), 256>>>(W2, w22, FF, EE, EE, 0,
                                                 (size_t)FF*EE, (size_t)F3*EE);
        convert_tok_kernel<<<dim3(EE / 32, VV / 32), dim3(32, 32)>>>(tok, tok2);
    }

    // ---- embedding ----
    {
        size_t n = (size_t)MM * EE;
        embed_kernel<<<(unsigned)((n + 255) / 256), 256>>>(idx, tok, pos, x);
    }

    // persistent grids: cap at 2 CTAs/SM * 148 SMs
    const int MAXCTA = 296;
    auto pgrid = [&](int N) { int t = (MM / 128) * (N / 128); return t < MAXCTA ? t : MAXCTA; };
    const int gQKV = pgrid(E3);
    const int gEc  = pgrid(EE);
    const int gFc  = pgrid(FF);
    const int gVc  = pgrid(VV);

    for (int l = 0; l < LL; l++) {
        ln_split_kernel<<<MM, 256>>>(x, ln1_g + (size_t)l * EE, ln1_b + (size_t)l * EE, xn2);
        mma_gemm<false, true><<<gQKV, 256, GEMM_SMEM>>>(xn2, wqkv2 + (size_t)l * E3 * E3,
                                                        nullptr, nullptr, qkv2, MM, E3, E3);
        attn_mma_kernel<<<dim3(TT / 128, HH, BB), 256, ATTN_SMEM>>>(qkv2, att2);
        mma_gemm<false, false><<<gEc, 256, GEMM_SMEM>>>(att2, wo2 + (size_t)l * E3 * EE,
                                                        bo + (size_t)l * EE, x, x, MM, EE, E3);
        ln_split_kernel<<<MM, 256>>>(x, ln2_g + (size_t)l * EE, ln2_b + (size_t)l * EE, xn2);
        mma_gemm<true, true><<<gFc, 256, GEMM_SMEM>>>(xn2, w12 + (size_t)l * E3 * FF,
                                                      b1 + (size_t)l * FF, nullptr, h42, MM, FF, E3);
        mma_gemm<false, false><<<gEc, 256, GEMM_SMEM>>>(h42, w22 + (size_t)l * F3 * EE,
                                                        b2 + (size_t)l * EE, x, x, MM, EE, F3);
    }

    ln_split_kernel<<<MM, 256>>>(x, lnf_g, lnf_b, xn2);
    mma_gemm<false, false><<<gVc, 256, GEMM_SMEM>>>(xn2, tok2, nullptr, nullptr, logits, MM, VV, E3);

    float* loss_ptr = out_holds_logits ? ((float*)d_out + (size_t)MM * VV)
                                       : (float*)d_out;
    if (!out_holds_logits || (long long)out_size > (long long)MM * VV) {
        loss_zero_kernel<<<1, 1>>>(loss_ptr);
        loss_kernel<<<MM, 256>>>(logits, targets, loss_ptr);
    }
}